// round 1
// baseline (speedup 1.0000x reference)
#include <cuda_runtime.h>

// Problem constants
constexpr int C   = 64;
constexpr int H   = 128;
constexpr int W   = 128;
constexpr int HW  = H * W;          // 16384
constexpr int B   = 8;
constexpr int C3  = 192;

// Scratch buffers (device globals; no allocation allowed)
__device__ float g_xp [B * C * HW];
__device__ float g_x1 [B * C * HW];
__device__ float g_x2 [B * C * HW];
__device__ float g_xfp[B * C * HW];
__device__ float g_xrp[B * C * HW];
__device__ float g_fxf[B * C * HW];
__device__ float g_fxr[B * C * HW];

// ---------------------------------------------------------------------------
// Kernel 1: pointwise projections.
//   xp = Wx@x + bx ; x1 = Wx1@xp + bx1 ; x2 = Wx2@xp + bx2
//   xfp = Wxf@xf + bxf ; xrp = Wxr@xr + bxr
// Block: 128 spatial positions of one image. 256 threads.
// Thread tile: 4 out-channels x 8 positions (positions interleaved by 16
// for conflict-free smem reads).
// smem: 5 weight mats [64][65] (pad), input tile [64][128], xp tile [64][128].
// ---------------------------------------------------------------------------

#define PROJ_W_STRIDE 65
#define PROJ_SMEM_FLOATS (5 * 64 * PROJ_W_STRIDE + 2 * 64 * 128)

__device__ __forceinline__ void proj_gemm(const float* __restrict__ sW,
                                          const float* __restrict__ gBias,
                                          const float* __restrict__ sIn,
                                          float acc[4][8], int o0, int wg) {
#pragma unroll
    for (int j = 0; j < 4; j++)
#pragma unroll
        for (int i = 0; i < 8; i++) acc[j][i] = 0.f;
    for (int c = 0; c < 64; c++) {
        float in[8];
#pragma unroll
        for (int i = 0; i < 8; i++) in[i] = sIn[c * 128 + wg + 16 * i];
        float wv[4];
#pragma unroll
        for (int j = 0; j < 4; j++) wv[j] = sW[(o0 + j) * PROJ_W_STRIDE + c];
#pragma unroll
        for (int j = 0; j < 4; j++)
#pragma unroll
            for (int i = 0; i < 8; i++) acc[j][i] += wv[j] * in[i];
    }
#pragma unroll
    for (int j = 0; j < 4; j++) {
        float bb = gBias[o0 + j];
#pragma unroll
        for (int i = 0; i < 8; i++) acc[j][i] += bb;
    }
}

__global__ __launch_bounds__(256) void proj_kernel(
    const float* __restrict__ x, const float* __restrict__ xf, const float* __restrict__ xr,
    const float* __restrict__ Wx,  const float* __restrict__ bx,
    const float* __restrict__ Wx1, const float* __restrict__ bx1,
    const float* __restrict__ Wx2, const float* __restrict__ bx2,
    const float* __restrict__ Wxf, const float* __restrict__ bxf,
    const float* __restrict__ Wxr, const float* __restrict__ bxr) {
    extern __shared__ float sm[];
    float* sWx  = sm;
    float* sWx1 = sWx  + 64 * PROJ_W_STRIDE;
    float* sWx2 = sWx1 + 64 * PROJ_W_STRIDE;
    float* sWxf = sWx2 + 64 * PROJ_W_STRIDE;
    float* sWxr = sWxf + 64 * PROJ_W_STRIDE;
    float* sIn  = sWxr + 64 * PROJ_W_STRIDE;   // [64][128]
    float* sXp  = sIn + 64 * 128;              // [64][128]

    const int tid = threadIdx.x;
    const int bp0 = blockIdx.x * 128;
    const int b   = bp0 >> 14;          // /16384
    const int p0  = bp0 & (HW - 1);
    const size_t gbase = (size_t)b * C * HW + p0;

    // Weights: coalesced global read, padded smem store (conflict-free).
    for (int i = tid; i < 4096; i += 256) {
        int o = i >> 6, c = i & 63;
        int s = o * PROJ_W_STRIDE + c;
        sWx [s] = Wx [i];
        sWx1[s] = Wx1[i];
        sWx2[s] = Wx2[i];
        sWxf[s] = Wxf[i];
        sWxr[s] = Wxr[i];
    }
    // Input tile x
    for (int i = tid; i < 8192; i += 256) {
        int c = i >> 7, p = i & 127;
        sIn[i] = x[gbase + (size_t)c * HW + p];
    }
    __syncthreads();

    const int og = tid >> 4;      // 0..15
    const int wg = tid & 15;      // 0..15
    const int o0 = og * 4;
    float acc[4][8];

    // xp
    proj_gemm(sWx, bx, sIn, acc, o0, wg);
#pragma unroll
    for (int j = 0; j < 4; j++)
#pragma unroll
        for (int i = 0; i < 8; i++) {
            int o = o0 + j, p = wg + 16 * i;
            sXp[o * 128 + p] = acc[j][i];
            g_xp[gbase + (size_t)o * HW + p] = acc[j][i];
        }
    __syncthreads();

    // x1, x2 (projections of xp)
    proj_gemm(sWx1, bx1, sXp, acc, o0, wg);
#pragma unroll
    for (int j = 0; j < 4; j++)
#pragma unroll
        for (int i = 0; i < 8; i++)
            g_x1[gbase + (size_t)(o0 + j) * HW + wg + 16 * i] = acc[j][i];
    proj_gemm(sWx2, bx2, sXp, acc, o0, wg);
#pragma unroll
    for (int j = 0; j < 4; j++)
#pragma unroll
        for (int i = 0; i < 8; i++)
            g_x2[gbase + (size_t)(o0 + j) * HW + wg + 16 * i] = acc[j][i];
    __syncthreads();

    // xfp
    for (int i = tid; i < 8192; i += 256) {
        int c = i >> 7, p = i & 127;
        sIn[i] = xf[gbase + (size_t)c * HW + p];
    }
    __syncthreads();
    proj_gemm(sWxf, bxf, sIn, acc, o0, wg);
#pragma unroll
    for (int j = 0; j < 4; j++)
#pragma unroll
        for (int i = 0; i < 8; i++)
            g_xfp[gbase + (size_t)(o0 + j) * HW + wg + 16 * i] = acc[j][i];
    __syncthreads();

    // xrp
    for (int i = tid; i < 8192; i += 256) {
        int c = i >> 7, p = i & 127;
        sIn[i] = xr[gbase + (size_t)c * HW + p];
    }
    __syncthreads();
    proj_gemm(sWxr, bxr, sIn, acc, o0, wg);
#pragma unroll
    for (int j = 0; j < 4; j++)
#pragma unroll
        for (int i = 0; i < 8; i++)
            g_xrp[gbase + (size_t)(o0 + j) * HW + wg + 16 * i] = acc[j][i];
}

// ---------------------------------------------------------------------------
// Kernel 2: per-(b,h) attention.
//   score[c][d] = sum_w A[c][w] * Bm[d][w]   (A=x1/x2, Bm=xfp/xrp)
//   feat [c][w] = sum_d score[c][d] * xp[d][w]
// One block per (b,h). 256 threads.
// Tiles padded to stride 129 (makes d-strided reads conflict-free).
// Score (stride 65) aliases the A-tile buffer after a sync.
// ---------------------------------------------------------------------------

#define ATTN_TS 129
#define ATTN_SMEM_FLOATS (3 * 64 * ATTN_TS)

__global__ __launch_bounds__(256) void attn_kernel() {
    extern __shared__ float sm[];
    float* sA = sm;                    // x1/x2 tile, later aliased by score
    float* sB = sA + 64 * ATTN_TS;     // xfp/xrp tile
    float* sP = sB + 64 * ATTN_TS;     // xp tile
    float* sS = sA;                    // score [64][65] (alias)

    const int h = blockIdx.x;
    const int b = blockIdx.y;
    const int tid = threadIdx.x;
    const size_t base = (size_t)b * C * HW + h * W;

    for (int i = tid; i < 8192; i += 256) {
        int c = i >> 7, w = i & 127;
        sP[c * ATTN_TS + w] = g_xp[base + (size_t)c * HW + w];
    }

    for (int pass = 0; pass < 2; pass++) {
        const float* gA = pass ? g_x2  : g_x1;
        const float* gB = pass ? g_xrp : g_xfp;
        float*       gO = pass ? g_fxr : g_fxf;

        for (int i = tid; i < 8192; i += 256) {
            int c = i >> 7, w = i & 127;
            sA[c * ATTN_TS + w] = gA[base + (size_t)c * HW + w];
            sB[c * ATTN_TS + w] = gB[base + (size_t)c * HW + w];
        }
        __syncthreads();

        // score GEMM: thread tile 4c x 4d, d interleaved by 16
        float sacc[4][4];
        {
            const int cg = tid >> 4, dg = tid & 15;
#pragma unroll
            for (int jc = 0; jc < 4; jc++)
#pragma unroll
                for (int jd = 0; jd < 4; jd++) sacc[jc][jd] = 0.f;
            for (int w = 0; w < 128; w++) {
                float a[4], bb[4];
#pragma unroll
                for (int jc = 0; jc < 4; jc++) a[jc]  = sA[(cg * 4 + jc) * ATTN_TS + w];
#pragma unroll
                for (int jd = 0; jd < 4; jd++) bb[jd] = sB[(dg + 16 * jd) * ATTN_TS + w];
#pragma unroll
                for (int jc = 0; jc < 4; jc++)
#pragma unroll
                    for (int jd = 0; jd < 4; jd++) sacc[jc][jd] += a[jc] * bb[jd];
            }
        }
        __syncthreads();   // done reading sA -> safe to alias with score
        {
            const int cg = tid >> 4, dg = tid & 15;
#pragma unroll
            for (int jc = 0; jc < 4; jc++)
#pragma unroll
                for (int jd = 0; jd < 4; jd++)
                    sS[(cg * 4 + jc) * 65 + dg + 16 * jd] = sacc[jc][jd];
        }
        __syncthreads();

        // feature GEMM: thread tile 4c x 8w
        {
            const int og = tid >> 4, wg = tid & 15;
            float facc[4][8];
#pragma unroll
            for (int jc = 0; jc < 4; jc++)
#pragma unroll
                for (int i = 0; i < 8; i++) facc[jc][i] = 0.f;
            for (int d = 0; d < 64; d++) {
                float p8[8];
#pragma unroll
                for (int i = 0; i < 8; i++) p8[i] = sP[d * ATTN_TS + wg + 16 * i];
                float sc[4];
#pragma unroll
                for (int jc = 0; jc < 4; jc++) sc[jc] = sS[(og * 4 + jc) * 65 + d];
#pragma unroll
                for (int jc = 0; jc < 4; jc++)
#pragma unroll
                    for (int i = 0; i < 8; i++) facc[jc][i] += sc[jc] * p8[i];
            }
#pragma unroll
            for (int jc = 0; jc < 4; jc++)
#pragma unroll
                for (int i = 0; i < 8; i++)
                    gO[base + (size_t)(og * 4 + jc) * HW + wg + 16 * i] = facc[jc][i];
        }
        __syncthreads();
    }
}

// ---------------------------------------------------------------------------
// Kernel 3: 3x3 conv (192->192, SAME) over concat[fxf, fxr, x] + BN + ReLU.
// Block: 64 out-ch x 64 width at fixed (b,h). 128 threads.
// Thread tile: 8 out-ch x 4 widths (widths interleaved by 16).
// K loop: 12 chunks of 16 input channels.
// smem: weights [64][145] (pad, coalesced 144-float runs per o), input [16][3][66].
// ---------------------------------------------------------------------------

#define CONV_WS 145
#define CONV_SMEM_FLOATS (64 * CONV_WS + 16 * 3 * 66)

__global__ __launch_bounds__(128) void conv_kernel(
    const float* __restrict__ x, const float* __restrict__ Wm,
    const float* __restrict__ bm, const float* __restrict__ gamma,
    const float* __restrict__ beta, const float* __restrict__ mean,
    const float* __restrict__ var, float* __restrict__ out) {
    extern __shared__ float sm[];
    float* swt = sm;                       // [64][145]
    float* sin = sm + 64 * CONV_WS;        // [16][3][66]

    const int tid = threadIdx.x;
    const int ot = blockIdx.x % 3, wt = blockIdx.x / 3;
    const int h = blockIdx.y, b = blockIdx.z;
    const int o0 = ot * 64, w0 = wt * 64;
    const int og = tid >> 4;   // 0..7 -> 8 out-ch each
    const int wg = tid & 15;   // 0..15 -> 4 widths each (stride 16)

    float acc[8][4];
#pragma unroll
    for (int j = 0; j < 8; j++)
#pragma unroll
        for (int i = 0; i < 4; i++) acc[j][i] = 0.f;

    for (int kc = 0; kc < 12; kc++) {
        // weights: per o, 144 contiguous floats (16 in-ch x 9 taps)
        for (int idx = tid; idx < 9216; idx += 128) {
            int o = idx / 144, rem = idx - o * 144;
            swt[o * CONV_WS + rem] = Wm[(size_t)(o0 + o) * 1728 + kc * 144 + rem];
        }
        // input: 16 channels x 3 rows x 66 cols, zero-padded halo
        for (int idx = tid; idx < 3168; idx += 128) {
            int ci = idx / 198, rem = idx - ci * 198;
            int r = rem / 66, cl = rem - r * 66;
            int row = h + r - 1, col = w0 + cl - 1;
            float v = 0.f;
            if (row >= 0 && row < H && col >= 0 && col < W) {
                int ch = kc * 16 + ci;
                const float* src;
                int cc;
                if (ch < 64)        { src = g_fxf; cc = ch; }
                else if (ch < 128)  { src = g_fxr; cc = ch - 64; }
                else                { src = x;     cc = ch - 128; }
                v = src[((size_t)(b * 64 + cc) * H + row) * W + col];
            }
            sin[idx] = v;
        }
        __syncthreads();

        for (int ci = 0; ci < 16; ci++) {
#pragma unroll
            for (int r = 0; r < 3; r++) {
                float inv[4][3];
#pragma unroll
                for (int i = 0; i < 4; i++)
#pragma unroll
                    for (int kw = 0; kw < 3; kw++)
                        inv[i][kw] = sin[ci * 198 + r * 66 + wg + 16 * i + kw];
#pragma unroll
                for (int kw = 0; kw < 3; kw++) {
                    float wv[8];
#pragma unroll
                    for (int j = 0; j < 8; j++)
                        wv[j] = swt[(og * 8 + j) * CONV_WS + ci * 9 + r * 3 + kw];
#pragma unroll
                    for (int j = 0; j < 8; j++)
#pragma unroll
                        for (int i = 0; i < 4; i++)
                            acc[j][i] += wv[j] * inv[i][kw];
                }
            }
        }
        __syncthreads();
    }

    // Epilogue: folded bias + BN + ReLU
#pragma unroll
    for (int j = 0; j < 8; j++) {
        int o = o0 + og * 8 + j;
        float sc = gamma[o] * rsqrtf(var[o] + 1e-4f);
        float bi = (bm[o] - mean[o]) * sc + beta[o];
#pragma unroll
        for (int i = 0; i < 4; i++) {
            float v = acc[j][i] * sc + bi;
            v = v > 0.f ? v : 0.f;
            out[(((size_t)b * C3 + o) * H + h) * W + w0 + wg + 16 * i] = v;
        }
    }
}

// ---------------------------------------------------------------------------

extern "C" void kernel_launch(void* const* d_in, const int* in_sizes, int n_in,
                              void* d_out, int out_size) {
    const float* x    = (const float*)d_in[0];
    const float* xf   = (const float*)d_in[1];
    const float* xr   = (const float*)d_in[2];
    const float* Wx   = (const float*)d_in[3];
    const float* bx   = (const float*)d_in[4];
    const float* Wx1  = (const float*)d_in[5];
    const float* bx1  = (const float*)d_in[6];
    const float* Wx2  = (const float*)d_in[7];
    const float* bx2  = (const float*)d_in[8];
    const float* Wxf  = (const float*)d_in[9];
    const float* bxf  = (const float*)d_in[10];
    const float* Wxr  = (const float*)d_in[11];
    const float* bxr  = (const float*)d_in[12];
    const float* Wm   = (const float*)d_in[13];
    const float* bm   = (const float*)d_in[14];
    const float* gam  = (const float*)d_in[15];
    const float* bet  = (const float*)d_in[16];
    const float* mean = (const float*)d_in[17];
    const float* var  = (const float*)d_in[18];
    float* out = (float*)d_out;

    const int proj_smem = PROJ_SMEM_FLOATS * 4;
    const int attn_smem = ATTN_SMEM_FLOATS * 4;
    const int conv_smem = CONV_SMEM_FLOATS * 4;
    cudaFuncSetAttribute(proj_kernel, cudaFuncAttributeMaxDynamicSharedMemorySize, proj_smem);
    cudaFuncSetAttribute(attn_kernel, cudaFuncAttributeMaxDynamicSharedMemorySize, attn_smem);
    cudaFuncSetAttribute(conv_kernel, cudaFuncAttributeMaxDynamicSharedMemorySize, conv_smem);

    proj_kernel<<<B * HW / 128, 256, proj_smem>>>(x, xf, xr, Wx, bx, Wx1, bx1,
                                                  Wx2, bx2, Wxf, bxf, Wxr, bxr);
    attn_kernel<<<dim3(H, B), 256, attn_smem>>>();
    conv_kernel<<<dim3(6, H, B), 128, conv_smem>>>(x, Wm, bm, gam, bet, mean, var, out);
}

// round 3
// speedup vs baseline: 2.7252x; 2.7252x over previous
#include <cuda_runtime.h>
#include <cuda_fp16.h>
#include <cstdint>

// Problem constants
constexpr int C   = 64;
constexpr int H   = 128;
constexpr int W   = 128;
constexpr int HW  = H * W;          // 16384
constexpr int B   = 8;
constexpr int C3  = 192;

// Scratch buffers (device globals; no allocation allowed)
__device__ float g_xp [B * C * HW];
__device__ float g_x1 [B * C * HW];
__device__ float g_x2 [B * C * HW];
__device__ float g_xfp[B * C * HW];
__device__ float g_xrp[B * C * HW];
__device__ float g_fxf[B * C * HW];
__device__ float g_fxr[B * C * HW];

// fp16 split-precision staging for the conv (channel-last input, chunked weights)
__device__ __half g_inh[(size_t)B * H * W * C3];   // [b][h][w][c] hi
__device__ __half g_inl[(size_t)B * H * W * C3];   // [b][h][w][c] lo
__device__ __half g_wh16[54 * 192 * 32];           // [kc][o][32] hi
__device__ __half g_wl16[54 * 192 * 32];           // [kc][o][32] lo

// ---------------------------------------------------------------------------
// Helpers
// ---------------------------------------------------------------------------
__device__ __forceinline__ void cpa16(void* dst, const void* src) {
    uint32_t d = (uint32_t)__cvta_generic_to_shared(dst);
    asm volatile("cp.async.cg.shared.global [%0], [%1], 16;" :: "r"(d), "l"(src));
}
#define CP_COMMIT() asm volatile("cp.async.commit_group;" ::: "memory")
#define CP_WAIT1()  asm volatile("cp.async.wait_group 1;" ::: "memory")

__device__ __forceinline__ void mma16816(float acc[4], uint32_t a0, uint32_t a1,
                                         uint32_t a2, uint32_t a3,
                                         uint32_t b0, uint32_t b1) {
    asm volatile(
        "mma.sync.aligned.m16n8k16.row.col.f32.f16.f16.f32 "
        "{%0,%1,%2,%3}, {%4,%5,%6,%7}, {%8,%9}, {%0,%1,%2,%3};"
        : "+f"(acc[0]), "+f"(acc[1]), "+f"(acc[2]), "+f"(acc[3])
        : "r"(a0), "r"(a1), "r"(a2), "r"(a3), "r"(b0), "r"(b1));
}

__device__ __forceinline__ uint32_t lds32(const __half* p) {
    return *(const uint32_t*)p;
}

// ---------------------------------------------------------------------------
// Kernel 1: pointwise projections (unchanged; fp32 register GEMM).
// ---------------------------------------------------------------------------

#define PROJ_W_STRIDE 65
#define PROJ_SMEM_FLOATS (5 * 64 * PROJ_W_STRIDE + 2 * 64 * 128)

__device__ __forceinline__ void proj_gemm(const float* __restrict__ sW,
                                          const float* __restrict__ gBias,
                                          const float* __restrict__ sIn,
                                          float acc[4][8], int o0, int wg) {
#pragma unroll
    for (int j = 0; j < 4; j++)
#pragma unroll
        for (int i = 0; i < 8; i++) acc[j][i] = 0.f;
    for (int c = 0; c < 64; c++) {
        float in[8];
#pragma unroll
        for (int i = 0; i < 8; i++) in[i] = sIn[c * 128 + wg + 16 * i];
        float wv[4];
#pragma unroll
        for (int j = 0; j < 4; j++) wv[j] = sW[(o0 + j) * PROJ_W_STRIDE + c];
#pragma unroll
        for (int j = 0; j < 4; j++)
#pragma unroll
            for (int i = 0; i < 8; i++) acc[j][i] += wv[j] * in[i];
    }
#pragma unroll
    for (int j = 0; j < 4; j++) {
        float bb = gBias[o0 + j];
#pragma unroll
        for (int i = 0; i < 8; i++) acc[j][i] += bb;
    }
}

__global__ __launch_bounds__(256) void proj_kernel(
    const float* __restrict__ x, const float* __restrict__ xf, const float* __restrict__ xr,
    const float* __restrict__ Wx,  const float* __restrict__ bx,
    const float* __restrict__ Wx1, const float* __restrict__ bx1,
    const float* __restrict__ Wx2, const float* __restrict__ bx2,
    const float* __restrict__ Wxf, const float* __restrict__ bxf,
    const float* __restrict__ Wxr, const float* __restrict__ bxr) {
    extern __shared__ float sm[];
    float* sWx  = sm;
    float* sWx1 = sWx  + 64 * PROJ_W_STRIDE;
    float* sWx2 = sWx1 + 64 * PROJ_W_STRIDE;
    float* sWxf = sWx2 + 64 * PROJ_W_STRIDE;
    float* sWxr = sWxf + 64 * PROJ_W_STRIDE;
    float* sIn  = sWxr + 64 * PROJ_W_STRIDE;   // [64][128]
    float* sXp  = sIn + 64 * 128;              // [64][128]

    const int tid = threadIdx.x;
    const int bp0 = blockIdx.x * 128;
    const int b   = bp0 >> 14;
    const int p0  = bp0 & (HW - 1);
    const size_t gbase = (size_t)b * C * HW + p0;

    for (int i = tid; i < 4096; i += 256) {
        int o = i >> 6, c = i & 63;
        int s = o * PROJ_W_STRIDE + c;
        sWx [s] = Wx [i];
        sWx1[s] = Wx1[i];
        sWx2[s] = Wx2[i];
        sWxf[s] = Wxf[i];
        sWxr[s] = Wxr[i];
    }
    for (int i = tid; i < 8192; i += 256) {
        int c = i >> 7, p = i & 127;
        sIn[i] = x[gbase + (size_t)c * HW + p];
    }
    __syncthreads();

    const int og = tid >> 4;
    const int wg = tid & 15;
    const int o0 = og * 4;
    float acc[4][8];

    proj_gemm(sWx, bx, sIn, acc, o0, wg);
#pragma unroll
    for (int j = 0; j < 4; j++)
#pragma unroll
        for (int i = 0; i < 8; i++) {
            int o = o0 + j, p = wg + 16 * i;
            sXp[o * 128 + p] = acc[j][i];
            g_xp[gbase + (size_t)o * HW + p] = acc[j][i];
        }
    __syncthreads();

    proj_gemm(sWx1, bx1, sXp, acc, o0, wg);
#pragma unroll
    for (int j = 0; j < 4; j++)
#pragma unroll
        for (int i = 0; i < 8; i++)
            g_x1[gbase + (size_t)(o0 + j) * HW + wg + 16 * i] = acc[j][i];
    proj_gemm(sWx2, bx2, sXp, acc, o0, wg);
#pragma unroll
    for (int j = 0; j < 4; j++)
#pragma unroll
        for (int i = 0; i < 8; i++)
            g_x2[gbase + (size_t)(o0 + j) * HW + wg + 16 * i] = acc[j][i];
    __syncthreads();

    for (int i = tid; i < 8192; i += 256) {
        int c = i >> 7, p = i & 127;
        sIn[i] = xf[gbase + (size_t)c * HW + p];
    }
    __syncthreads();
    proj_gemm(sWxf, bxf, sIn, acc, o0, wg);
#pragma unroll
    for (int j = 0; j < 4; j++)
#pragma unroll
        for (int i = 0; i < 8; i++)
            g_xfp[gbase + (size_t)(o0 + j) * HW + wg + 16 * i] = acc[j][i];
    __syncthreads();

    for (int i = tid; i < 8192; i += 256) {
        int c = i >> 7, p = i & 127;
        sIn[i] = xr[gbase + (size_t)c * HW + p];
    }
    __syncthreads();
    proj_gemm(sWxr, bxr, sIn, acc, o0, wg);
#pragma unroll
    for (int j = 0; j < 4; j++)
#pragma unroll
        for (int i = 0; i < 8; i++)
            g_xrp[gbase + (size_t)(o0 + j) * HW + wg + 16 * i] = acc[j][i];
}

// ---------------------------------------------------------------------------
// Kernel 2: per-(b,h) attention (unchanged).
// ---------------------------------------------------------------------------

#define ATTN_TS 129
#define ATTN_SMEM_FLOATS (3 * 64 * ATTN_TS)

__global__ __launch_bounds__(256) void attn_kernel() {
    extern __shared__ float sm[];
    float* sA = sm;
    float* sB = sA + 64 * ATTN_TS;
    float* sP = sB + 64 * ATTN_TS;
    float* sS = sA;

    const int h = blockIdx.x;
    const int b = blockIdx.y;
    const int tid = threadIdx.x;
    const size_t base = (size_t)b * C * HW + h * W;

    for (int i = tid; i < 8192; i += 256) {
        int c = i >> 7, w = i & 127;
        sP[c * ATTN_TS + w] = g_xp[base + (size_t)c * HW + w];
    }

    for (int pass = 0; pass < 2; pass++) {
        const float* gA = pass ? g_x2  : g_x1;
        const float* gB = pass ? g_xrp : g_xfp;
        float*       gO = pass ? g_fxr : g_fxf;

        for (int i = tid; i < 8192; i += 256) {
            int c = i >> 7, w = i & 127;
            sA[c * ATTN_TS + w] = gA[base + (size_t)c * HW + w];
            sB[c * ATTN_TS + w] = gB[base + (size_t)c * HW + w];
        }
        __syncthreads();

        float sacc[4][4];
        {
            const int cg = tid >> 4, dg = tid & 15;
#pragma unroll
            for (int jc = 0; jc < 4; jc++)
#pragma unroll
                for (int jd = 0; jd < 4; jd++) sacc[jc][jd] = 0.f;
            for (int w = 0; w < 128; w++) {
                float a[4], bb[4];
#pragma unroll
                for (int jc = 0; jc < 4; jc++) a[jc]  = sA[(cg * 4 + jc) * ATTN_TS + w];
#pragma unroll
                for (int jd = 0; jd < 4; jd++) bb[jd] = sB[(dg + 16 * jd) * ATTN_TS + w];
#pragma unroll
                for (int jc = 0; jc < 4; jc++)
#pragma unroll
                    for (int jd = 0; jd < 4; jd++) sacc[jc][jd] += a[jc] * bb[jd];
            }
        }
        __syncthreads();
        {
            const int cg = tid >> 4, dg = tid & 15;
#pragma unroll
            for (int jc = 0; jc < 4; jc++)
#pragma unroll
                for (int jd = 0; jd < 4; jd++)
                    sS[(cg * 4 + jc) * 65 + dg + 16 * jd] = sacc[jc][jd];
        }
        __syncthreads();

        {
            const int og = tid >> 4, wg = tid & 15;
            float facc[4][8];
#pragma unroll
            for (int jc = 0; jc < 4; jc++)
#pragma unroll
                for (int i = 0; i < 8; i++) facc[jc][i] = 0.f;
            for (int d = 0; d < 64; d++) {
                float p8[8];
#pragma unroll
                for (int i = 0; i < 8; i++) p8[i] = sP[d * ATTN_TS + wg + 16 * i];
                float sc[4];
#pragma unroll
                for (int jc = 0; jc < 4; jc++) sc[jc] = sS[(og * 4 + jc) * 65 + d];
#pragma unroll
                for (int jc = 0; jc < 4; jc++)
#pragma unroll
                    for (int i = 0; i < 8; i++) facc[jc][i] += sc[jc] * p8[i];
            }
#pragma unroll
            for (int jc = 0; jc < 4; jc++)
#pragma unroll
                for (int i = 0; i < 8; i++)
                    gO[base + (size_t)(og * 4 + jc) * HW + wg + 16 * i] = facc[jc][i];
        }
        __syncthreads();
    }
}

// ---------------------------------------------------------------------------
// Kernel 3a: weight prep. K order: k = tap*192 + ch; chunk kc covers 32 ch.
// g_wh16/g_wl16[kc][o][j] fp16 hi/lo, contiguous 64B rows for cp.async.
// ---------------------------------------------------------------------------
__global__ void wprep_kernel(const float* __restrict__ Wm) {
    const int kc = blockIdx.x;       // 0..53
    const int o  = threadIdx.x;      // 0..191
    const int tap = kc / 6;
    const int ch0 = (kc - tap * 6) * 32;
#pragma unroll
    for (int j = 0; j < 32; j++) {
        float v  = Wm[((size_t)o * 192 + ch0 + j) * 9 + tap];
        __half hi = __float2half_rn(v);
        __half lo = __float2half_rn(v - __half2float(hi));
        size_t d = ((size_t)kc * 192 + o) * 32 + j;
        g_wh16[d] = hi;
        g_wl16[d] = lo;
    }
}

// ---------------------------------------------------------------------------
// Kernel 3b: input prep. concat[fxf,fxr,x] -> channel-last fp16 hi/lo.
// ---------------------------------------------------------------------------
__global__ void inprep_kernel(const float* __restrict__ x) {
    const int h = blockIdx.x, b = blockIdx.y;
    const int c = threadIdx.x;   // 0..191
    const float* src;
    if (c < 64)        src = g_fxf + ((size_t)b * 64 + c)       * HW + (size_t)h * W;
    else if (c < 128)  src = g_fxr + ((size_t)b * 64 + c - 64)  * HW + (size_t)h * W;
    else               src = x     + ((size_t)b * 64 + c - 128) * HW + (size_t)h * W;
    size_t dbase = ((size_t)(b * 128 + h) * 128) * 192 + c;
    for (int w = 0; w < 128; w++) {
        float v = src[w];
        __half hi = __float2half_rn(v);
        __half lo = __float2half_rn(v - __half2float(hi));
        g_inh[dbase + (size_t)w * 192] = hi;
        g_inl[dbase + (size_t)w * 192] = lo;
    }
}

// ---------------------------------------------------------------------------
// Kernel 3c: fp16 split mma.sync implicit-GEMM conv + BN + ReLU.
// One CTA per (b,h). GEMM: M=192 (out-ch, A=weights), N=128 (w, B=input),
// K=1728 in 54 chunks of 32. hi*hi + lo*hi + hi*lo, fp32 accumulate.
// 8 warps: warp tile 96(o) x 32(w). Double-buffered cp.async staging.
// smem rows stride 40 halfs -> conflict-free fragment LDS.
// ---------------------------------------------------------------------------

#define AST 40                       // smem row stride in halfs
#define A_TILE (192 * AST)           // 7680 halfs
#define B_TILE (128 * AST)           // 5120 halfs
#define CONV_SMEM_BYTES ((2 * A_TILE * 2 + 2 * B_TILE * 2) * 2 + 384 * 4)

__global__ __launch_bounds__(256, 1) void conv_mma_kernel(
    const float* __restrict__ bm, const float* __restrict__ gamma,
    const float* __restrict__ beta, const float* __restrict__ mean,
    const float* __restrict__ var, float* __restrict__ out) {
    extern __shared__ __align__(16) __half smh[];
    __half* sAh = smh;                       // [2][A_TILE]
    __half* sAl = sAh + 2 * A_TILE;
    __half* sBh = sAl + 2 * A_TILE;          // [2][B_TILE]
    __half* sBl = sBh + 2 * B_TILE;
    float* ssc = (float*)(sBl + 2 * B_TILE);
    float* sbi = ssc + 192;

    const int tid = threadIdx.x;
    const int h = blockIdx.x, b = blockIdx.y;

    if (tid < 192) {
        float scv = gamma[tid] * rsqrtf(var[tid] + 1e-4f);
        ssc[tid] = scv;
        sbi[tid] = (bm[tid] - mean[tid]) * scv + beta[tid];
    }

    const int lane = tid & 31;
    const int wid = tid >> 5;
    const int wm = wid & 1;          // 2 M-groups of 96
    const int wn = wid >> 1;         // 4 N-groups of 32
    const int lr = lane >> 2;        // fragment row 0..7
    const int lc2 = (lane & 3) * 2;  // fragment col pair

    float acc[6][4][4];
#pragma unroll
    for (int mt = 0; mt < 6; mt++)
#pragma unroll
        for (int nt = 0; nt < 4; nt++)
#pragma unroll
            for (int i = 0; i < 4; i++) acc[mt][nt][i] = 0.f;

    auto stage = [&](int kc, int buf) {
        const int tap = kc / 6;
        const int ch0 = (kc - tap * 6) * 32;
        const int dh = tap / 3 - 1;
        const int dw = tap - (tap / 3) * 3 - 1;
        const int row = h + dh;
        const bool rok = ((unsigned)row < 128u);
        const __half* wh = g_wh16 + (size_t)kc * 6144;
        const __half* wl = g_wl16 + (size_t)kc * 6144;
        // A = weights: 192 rows x 4 granules, hi+lo
#pragma unroll
        for (int i = 0; i < 3; i++) {
            int idx = tid + i * 256;          // 0..767
            int r = idx >> 2, g = idx & 3;
            cpa16(sAh + buf * A_TILE + r * AST + g * 8, wh + r * 32 + g * 8);
            cpa16(sAl + buf * A_TILE + r * AST + g * 8, wl + r * 32 + g * 8);
        }
        // B = input rows: 128 rows x 4 granules, hi+lo, halo zero-fill
        const size_t rowbase = ((size_t)(b * 128 + row) * 128) * 192;
#pragma unroll
        for (int i = 0; i < 2; i++) {
            int idx = tid + i * 256;          // 0..511
            int r = idx >> 2, g = idx & 3;
            int wsrc = r + dw;
            bool ok = rok && ((unsigned)wsrc < 128u);
            __half* dh_ = sBh + buf * B_TILE + r * AST + g * 8;
            __half* dl_ = sBl + buf * B_TILE + r * AST + g * 8;
            if (ok) {
                size_t s = rowbase + (size_t)wsrc * 192 + ch0 + g * 8;
                cpa16(dh_, g_inh + s);
                cpa16(dl_, g_inl + s);
            } else {
                *(uint4*)dh_ = make_uint4(0, 0, 0, 0);
                *(uint4*)dl_ = make_uint4(0, 0, 0, 0);
            }
        }
    };

    stage(0, 0);
    CP_COMMIT();

    for (int kc = 0; kc < 54; kc++) {
        const int buf = kc & 1;
        if (kc < 53) stage(kc + 1, (kc + 1) & 1);
        CP_COMMIT();
        CP_WAIT1();
        __syncthreads();

        const __half* bAh = sAh + buf * A_TILE;
        const __half* bAl = sAl + buf * A_TILE;
        const __half* bBh = sBh + buf * B_TILE;
        const __half* bBl = sBl + buf * B_TILE;

#pragma unroll
        for (int ks = 0; ks < 2; ks++) {
            const int ko = ks * 16 + lc2;
            uint32_t bh[4][2], bl[4][2];
#pragma unroll
            for (int nt = 0; nt < 4; nt++) {
                int n = wn * 32 + nt * 8 + lr;
                bh[nt][0] = lds32(bBh + n * AST + ko);
                bh[nt][1] = lds32(bBh + n * AST + ko + 8);
                bl[nt][0] = lds32(bBl + n * AST + ko);
                bl[nt][1] = lds32(bBl + n * AST + ko + 8);
            }
#pragma unroll
            for (int mt = 0; mt < 6; mt++) {
                int m = wm * 96 + mt * 16 + lr;
                const __half* pa = bAh + m * AST + ks * 16 + lc2;
                uint32_t ah0 = lds32(pa);
                uint32_t ah1 = lds32(pa + 8 * AST);
                uint32_t ah2 = lds32(pa + 8);
                uint32_t ah3 = lds32(pa + 8 * AST + 8);
#pragma unroll
                for (int nt = 0; nt < 4; nt++)
                    mma16816(acc[mt][nt], ah0, ah1, ah2, ah3, bh[nt][0], bh[nt][1]);
                const __half* pl = bAl + m * AST + ks * 16 + lc2;
                uint32_t al0 = lds32(pl);
                uint32_t al1 = lds32(pl + 8 * AST);
                uint32_t al2 = lds32(pl + 8);
                uint32_t al3 = lds32(pl + 8 * AST + 8);
#pragma unroll
                for (int nt = 0; nt < 4; nt++)
                    mma16816(acc[mt][nt], al0, al1, al2, al3, bh[nt][0], bh[nt][1]);
#pragma unroll
                for (int nt = 0; nt < 4; nt++)
                    mma16816(acc[mt][nt], ah0, ah1, ah2, ah3, bl[nt][0], bl[nt][1]);
            }
        }
        __syncthreads();
    }

    // Epilogue: BN + ReLU, direct stores (float2 per fragment row)
#pragma unroll
    for (int mt = 0; mt < 6; mt++) {
        int o0 = wm * 96 + mt * 16 + lr;
        float s0 = ssc[o0],     bi0 = sbi[o0];
        float s1 = ssc[o0 + 8], bi1 = sbi[o0 + 8];
#pragma unroll
        for (int nt = 0; nt < 4; nt++) {
            int wcol = wn * 32 + nt * 8 + lc2;
            float2 v0, v1;
            v0.x = fmaxf(acc[mt][nt][0] * s0 + bi0, 0.f);
            v0.y = fmaxf(acc[mt][nt][1] * s0 + bi0, 0.f);
            v1.x = fmaxf(acc[mt][nt][2] * s1 + bi1, 0.f);
            v1.y = fmaxf(acc[mt][nt][3] * s1 + bi1, 0.f);
            size_t p0 = (((size_t)b * C3 + o0)     * H + h) * W + wcol;
            size_t p1 = (((size_t)b * C3 + o0 + 8) * H + h) * W + wcol;
            *(float2*)(out + p0) = v0;
            *(float2*)(out + p1) = v1;
        }
    }
}

// ---------------------------------------------------------------------------

extern "C" void kernel_launch(void* const* d_in, const int* in_sizes, int n_in,
                              void* d_out, int out_size) {
    const float* x    = (const float*)d_in[0];
    const float* xf   = (const float*)d_in[1];
    const float* xr   = (const float*)d_in[2];
    const float* Wx   = (const float*)d_in[3];
    const float* bx   = (const float*)d_in[4];
    const float* Wx1  = (const float*)d_in[5];
    const float* bx1  = (const float*)d_in[6];
    const float* Wx2  = (const float*)d_in[7];
    const float* bx2  = (const float*)d_in[8];
    const float* Wxf  = (const float*)d_in[9];
    const float* bxf  = (const float*)d_in[10];
    const float* Wxr  = (const float*)d_in[11];
    const float* bxr  = (const float*)d_in[12];
    const float* Wm   = (const float*)d_in[13];
    const float* bm   = (const float*)d_in[14];
    const float* gam  = (const float*)d_in[15];
    const float* bet  = (const float*)d_in[16];
    const float* mean = (const float*)d_in[17];
    const float* var  = (const float*)d_in[18];
    float* out = (float*)d_out;

    const int proj_smem = PROJ_SMEM_FLOATS * 4;
    const int attn_smem = ATTN_SMEM_FLOATS * 4;
    const int conv_smem = CONV_SMEM_BYTES;
    cudaFuncSetAttribute(proj_kernel, cudaFuncAttributeMaxDynamicSharedMemorySize, proj_smem);
    cudaFuncSetAttribute(attn_kernel, cudaFuncAttributeMaxDynamicSharedMemorySize, attn_smem);
    cudaFuncSetAttribute(conv_mma_kernel, cudaFuncAttributeMaxDynamicSharedMemorySize, conv_smem);

    proj_kernel<<<B * HW / 128, 256, proj_smem>>>(x, xf, xr, Wx, bx, Wx1, bx1,
                                                  Wx2, bx2, Wxf, bxf, Wxr, bxr);
    wprep_kernel<<<54, 192>>>(Wm);
    attn_kernel<<<dim3(H, B), 256, attn_smem>>>();
    inprep_kernel<<<dim3(H, B), 192>>>(x);
    conv_mma_kernel<<<dim3(H, B), 256, conv_smem>>>(bm, gam, bet, mean, var, out);
}

// round 4
// speedup vs baseline: 3.2527x; 1.1936x over previous
#include <cuda_runtime.h>
#include <cuda_fp16.h>
#include <cstdint>

// Problem constants
constexpr int C   = 64;
constexpr int H   = 128;
constexpr int W   = 128;
constexpr int HW  = H * W;          // 16384
constexpr int B   = 8;
constexpr int C3  = 192;

// Scratch buffers (device globals; no allocation allowed)
__device__ float g_xp [B * C * HW];
__device__ float g_x1 [B * C * HW];
__device__ float g_x2 [B * C * HW];
__device__ float g_xfp[B * C * HW];
__device__ float g_xrp[B * C * HW];
__device__ float g_fxf[B * C * HW];
__device__ float g_fxr[B * C * HW];

// fp16 split-precision staging for the conv (channel-last input, chunked weights)
__device__ __half g_inh[(size_t)B * H * W * C3];   // [b][h][w][c] hi
__device__ __half g_inl[(size_t)B * H * W * C3];   // [b][h][w][c] lo
__device__ __half g_wh16[54 * 192 * 32];           // [kc][o][32] hi
__device__ __half g_wl16[54 * 192 * 32];           // [kc][o][32] lo

// ---------------------------------------------------------------------------
// Helpers
// ---------------------------------------------------------------------------
__device__ __forceinline__ void cpa16(void* dst, const void* src) {
    uint32_t d = (uint32_t)__cvta_generic_to_shared(dst);
    asm volatile("cp.async.cg.shared.global [%0], [%1], 16;" :: "r"(d), "l"(src));
}
#define CP_COMMIT() asm volatile("cp.async.commit_group;" ::: "memory")
#define CP_WAIT1()  asm volatile("cp.async.wait_group 1;" ::: "memory")

__device__ __forceinline__ void mma16816(float acc[4], uint32_t a0, uint32_t a1,
                                         uint32_t a2, uint32_t a3,
                                         uint32_t b0, uint32_t b1) {
    asm volatile(
        "mma.sync.aligned.m16n8k16.row.col.f32.f16.f16.f32 "
        "{%0,%1,%2,%3}, {%4,%5,%6,%7}, {%8,%9}, {%0,%1,%2,%3};"
        : "+f"(acc[0]), "+f"(acc[1]), "+f"(acc[2]), "+f"(acc[3])
        : "r"(a0), "r"(a1), "r"(a2), "r"(a3), "r"(b0), "r"(b1));
}

__device__ __forceinline__ void ldsm4(uint32_t& r0, uint32_t& r1, uint32_t& r2,
                                      uint32_t& r3, const __half* p) {
    uint32_t a = (uint32_t)__cvta_generic_to_shared(p);
    asm volatile("ldmatrix.sync.aligned.m8n8.x4.shared.b16 {%0,%1,%2,%3}, [%4];"
                 : "=r"(r0), "=r"(r1), "=r"(r2), "=r"(r3) : "r"(a));
}

// ---------------------------------------------------------------------------
// Kernel 1: pointwise projections (fp32 register GEMM).
// smem: 5 weight mats transposed [c][o] with XOR swizzle (80KB) + one shared
// 64x128 tile (32KB) that holds x, then xp (aliased), then xf, then xr.
// Total ~112.5KB -> 2 CTAs/SM.
// ---------------------------------------------------------------------------

#define WIDX(o, c) (((c) << 6) | ((o) ^ ((c) & 31)))
#define PROJ_SMEM_FLOATS (5 * 4096 + 64 * 128)

__device__ __forceinline__ void proj_gemm(const float* __restrict__ sW,
                                          const float* __restrict__ sIn,
                                          float acc[4][8], int o0, int wg) {
#pragma unroll
    for (int j = 0; j < 4; j++)
#pragma unroll
        for (int i = 0; i < 8; i++) acc[j][i] = 0.f;
    for (int c = 0; c < 64; c++) {
        float in[8];
#pragma unroll
        for (int i = 0; i < 8; i++) in[i] = sIn[c * 128 + wg + 16 * i];
        float wv[4];
#pragma unroll
        for (int j = 0; j < 4; j++) wv[j] = sW[WIDX(o0 + j, c)];
#pragma unroll
        for (int j = 0; j < 4; j++)
#pragma unroll
            for (int i = 0; i < 8; i++) acc[j][i] += wv[j] * in[i];
    }
}

__global__ __launch_bounds__(256, 2) void proj_kernel(
    const float* __restrict__ x, const float* __restrict__ xf, const float* __restrict__ xr,
    const float* __restrict__ Wx,  const float* __restrict__ bx,
    const float* __restrict__ Wx1, const float* __restrict__ bx1,
    const float* __restrict__ Wx2, const float* __restrict__ bx2,
    const float* __restrict__ Wxf, const float* __restrict__ bxf,
    const float* __restrict__ Wxr, const float* __restrict__ bxr) {
    extern __shared__ float sm[];
    float* sWx  = sm;
    float* sWx1 = sWx  + 4096;
    float* sWx2 = sWx1 + 4096;
    float* sWxf = sWx2 + 4096;
    float* sWxr = sWxf + 4096;
    float* sIn  = sWxr + 4096;   // [64][128], reused for x / xp / xf / xr

    const int tid = threadIdx.x;
    const int bp0 = blockIdx.x * 128;
    const int b   = bp0 >> 14;
    const int p0  = bp0 & (HW - 1);
    const size_t gbase = (size_t)b * C * HW + p0;

    // Weights: coalesced global read; XOR-swizzled transposed store (conflict-free).
    for (int i = tid; i < 4096; i += 256) {
        int o = i >> 6, c = i & 63;
        int s = WIDX(o, c);
        sWx [s] = Wx [i];
        sWx1[s] = Wx1[i];
        sWx2[s] = Wx2[i];
        sWxf[s] = Wxf[i];
        sWxr[s] = Wxr[i];
    }
    for (int i = tid; i < 8192; i += 256) {
        int c = i >> 7, p = i & 127;
        sIn[i] = x[gbase + (size_t)c * HW + p];
    }
    __syncthreads();

    const int og = tid >> 4;
    const int wg = tid & 15;
    const int o0 = og * 4;
    float acc[4][8];

    // xp
    proj_gemm(sWx, sIn, acc, o0, wg);
    __syncthreads();                 // everyone done reading x
#pragma unroll
    for (int j = 0; j < 4; j++) {
        float bb = __ldg(bx + o0 + j);
#pragma unroll
        for (int i = 0; i < 8; i++) {
            int o = o0 + j, p = wg + 16 * i;
            float v = acc[j][i] + bb;
            sIn[o * 128 + p] = v;    // alias: tile now holds xp
            g_xp[gbase + (size_t)o * HW + p] = v;
        }
    }
    __syncthreads();

    // x1, x2 (projections of xp)
    proj_gemm(sWx1, sIn, acc, o0, wg);
#pragma unroll
    for (int j = 0; j < 4; j++) {
        float bb = __ldg(bx1 + o0 + j);
#pragma unroll
        for (int i = 0; i < 8; i++)
            g_x1[gbase + (size_t)(o0 + j) * HW + wg + 16 * i] = acc[j][i] + bb;
    }
    proj_gemm(sWx2, sIn, acc, o0, wg);
    __syncthreads();                 // done reading xp
#pragma unroll
    for (int j = 0; j < 4; j++) {
        float bb = __ldg(bx2 + o0 + j);
#pragma unroll
        for (int i = 0; i < 8; i++)
            g_x2[gbase + (size_t)(o0 + j) * HW + wg + 16 * i] = acc[j][i] + bb;
    }

    // xfp
    for (int i = tid; i < 8192; i += 256) {
        int c = i >> 7, p = i & 127;
        sIn[i] = xf[gbase + (size_t)c * HW + p];
    }
    __syncthreads();
    proj_gemm(sWxf, sIn, acc, o0, wg);
    __syncthreads();
#pragma unroll
    for (int j = 0; j < 4; j++) {
        float bb = __ldg(bxf + o0 + j);
#pragma unroll
        for (int i = 0; i < 8; i++)
            g_xfp[gbase + (size_t)(o0 + j) * HW + wg + 16 * i] = acc[j][i] + bb;
    }

    // xrp
    for (int i = tid; i < 8192; i += 256) {
        int c = i >> 7, p = i & 127;
        sIn[i] = xr[gbase + (size_t)c * HW + p];
    }
    __syncthreads();
    proj_gemm(sWxr, sIn, acc, o0, wg);
#pragma unroll
    for (int j = 0; j < 4; j++) {
        float bb = __ldg(bxr + o0 + j);
#pragma unroll
        for (int i = 0; i < 8; i++)
            g_xrp[gbase + (size_t)(o0 + j) * HW + wg + 16 * i] = acc[j][i] + bb;
    }
}

// ---------------------------------------------------------------------------
// Kernel 2: per-(b,h) attention (unchanged).
// ---------------------------------------------------------------------------

#define ATTN_TS 129
#define ATTN_SMEM_FLOATS (3 * 64 * ATTN_TS)

__global__ __launch_bounds__(256) void attn_kernel() {
    extern __shared__ float sm[];
    float* sA = sm;
    float* sB = sA + 64 * ATTN_TS;
    float* sP = sB + 64 * ATTN_TS;
    float* sS = sA;

    const int h = blockIdx.x;
    const int b = blockIdx.y;
    const int tid = threadIdx.x;
    const size_t base = (size_t)b * C * HW + h * W;

    for (int i = tid; i < 8192; i += 256) {
        int c = i >> 7, w = i & 127;
        sP[c * ATTN_TS + w] = g_xp[base + (size_t)c * HW + w];
    }

    for (int pass = 0; pass < 2; pass++) {
        const float* gA = pass ? g_x2  : g_x1;
        const float* gB = pass ? g_xrp : g_xfp;
        float*       gO = pass ? g_fxr : g_fxf;

        for (int i = tid; i < 8192; i += 256) {
            int c = i >> 7, w = i & 127;
            sA[c * ATTN_TS + w] = gA[base + (size_t)c * HW + w];
            sB[c * ATTN_TS + w] = gB[base + (size_t)c * HW + w];
        }
        __syncthreads();

        float sacc[4][4];
        {
            const int cg = tid >> 4, dg = tid & 15;
#pragma unroll
            for (int jc = 0; jc < 4; jc++)
#pragma unroll
                for (int jd = 0; jd < 4; jd++) sacc[jc][jd] = 0.f;
            for (int w = 0; w < 128; w++) {
                float a[4], bb[4];
#pragma unroll
                for (int jc = 0; jc < 4; jc++) a[jc]  = sA[(cg * 4 + jc) * ATTN_TS + w];
#pragma unroll
                for (int jd = 0; jd < 4; jd++) bb[jd] = sB[(dg + 16 * jd) * ATTN_TS + w];
#pragma unroll
                for (int jc = 0; jc < 4; jc++)
#pragma unroll
                    for (int jd = 0; jd < 4; jd++) sacc[jc][jd] += a[jc] * bb[jd];
            }
        }
        __syncthreads();
        {
            const int cg = tid >> 4, dg = tid & 15;
#pragma unroll
            for (int jc = 0; jc < 4; jc++)
#pragma unroll
                for (int jd = 0; jd < 4; jd++)
                    sS[(cg * 4 + jc) * 65 + dg + 16 * jd] = sacc[jc][jd];
        }
        __syncthreads();

        {
            const int og = tid >> 4, wg = tid & 15;
            float facc[4][8];
#pragma unroll
            for (int jc = 0; jc < 4; jc++)
#pragma unroll
                for (int i = 0; i < 8; i++) facc[jc][i] = 0.f;
            for (int d = 0; d < 64; d++) {
                float p8[8];
#pragma unroll
                for (int i = 0; i < 8; i++) p8[i] = sP[d * ATTN_TS + wg + 16 * i];
                float sc[4];
#pragma unroll
                for (int jc = 0; jc < 4; jc++) sc[jc] = sS[(og * 4 + jc) * 65 + d];
#pragma unroll
                for (int jc = 0; jc < 4; jc++)
#pragma unroll
                    for (int i = 0; i < 8; i++) facc[jc][i] += sc[jc] * p8[i];
            }
#pragma unroll
            for (int jc = 0; jc < 4; jc++)
#pragma unroll
                for (int i = 0; i < 8; i++)
                    gO[base + (size_t)(og * 4 + jc) * HW + wg + 16 * i] = facc[jc][i];
        }
        __syncthreads();
    }
}

// ---------------------------------------------------------------------------
// Kernel 3a: weight prep (unchanged).
// ---------------------------------------------------------------------------
__global__ void wprep_kernel(const float* __restrict__ Wm) {
    const int kc = blockIdx.x;       // 0..53
    const int o  = threadIdx.x;      // 0..191
    const int tap = kc / 6;
    const int ch0 = (kc - tap * 6) * 32;
#pragma unroll
    for (int j = 0; j < 32; j++) {
        float v  = Wm[((size_t)o * 192 + ch0 + j) * 9 + tap];
        __half hi = __float2half_rn(v);
        __half lo = __float2half_rn(v - __half2float(hi));
        size_t d = ((size_t)kc * 192 + o) * 32 + j;
        g_wh16[d] = hi;
        g_wl16[d] = lo;
    }
}

// ---------------------------------------------------------------------------
// Kernel 3b: input prep via smem transpose.
// Load [c][w] with coalesced float4, store channel-last packed half2 (uint32).
// ---------------------------------------------------------------------------
#define INPREP_SMEM_FLOATS (192 * 129)

__global__ __launch_bounds__(256) void inprep_kernel(const float* __restrict__ x) {
    extern __shared__ float s[];     // [192][129]
    const int h = blockIdx.x, b = blockIdx.y;
    const int tid = threadIdx.x;

    // coalesced loads: 192 channels x 32 float4
    for (int idx = tid; idx < 192 * 32; idx += 256) {
        int c = idx >> 5, q4 = idx & 31;
        const float* src;
        if (c < 64)        src = g_fxf + ((size_t)b * 64 + c)       * HW + (size_t)h * W;
        else if (c < 128)  src = g_fxr + ((size_t)b * 64 + c - 64)  * HW + (size_t)h * W;
        else               src = x     + ((size_t)b * 64 + c - 128) * HW + (size_t)h * W;
        float4 v = *(const float4*)(src + q4 * 4);
        float* d = s + c * 129 + q4 * 4;
        d[0] = v.x; d[1] = v.y; d[2] = v.z; d[3] = v.w;
    }
    __syncthreads();

    // transpose + split + packed stores: 128 w x 96 half2 words
    uint32_t* outh = (uint32_t*)g_inh;
    uint32_t* outl = (uint32_t*)g_inl;
    const size_t wbase = ((size_t)(b * 128 + h) * 128) * 96;
    for (int idx = tid; idx < 128 * 96; idx += 256) {
        int w = idx / 96, q = idx - w * 96;
        int c = q * 2;
        float v0 = s[c * 129 + w];
        float v1 = s[(c + 1) * 129 + w];
        __half h0 = __float2half_rn(v0);
        __half h1 = __float2half_rn(v1);
        __half l0 = __float2half_rn(v0 - __half2float(h0));
        __half l1 = __float2half_rn(v1 - __half2float(h1));
        __half2 ph = __halves2half2(h0, h1);
        __half2 pl = __halves2half2(l0, l1);
        outh[wbase + (size_t)w * 96 + q] = *(uint32_t*)&ph;
        outl[wbase + (size_t)w * 96 + q] = *(uint32_t*)&pl;
    }
}

// ---------------------------------------------------------------------------
// Kernel 3c: fp16 split mma.sync implicit-GEMM conv + BN + ReLU.
// ldmatrix.x4 fragment loads; double-buffered cp.async; 2 CTAs/SM.
// ---------------------------------------------------------------------------

#define AST 40                       // smem row stride in halfs
#define A_TILE (192 * AST)           // 7680 halfs
#define B_TILE (128 * AST)           // 5120 halfs
#define CONV_SMEM_BYTES ((2 * A_TILE * 2 + 2 * B_TILE * 2) * 2 + 384 * 4)

__global__ __launch_bounds__(256, 2) void conv_mma_kernel(
    const float* __restrict__ bm, const float* __restrict__ gamma,
    const float* __restrict__ beta, const float* __restrict__ mean,
    const float* __restrict__ var, float* __restrict__ out) {
    extern __shared__ __align__(16) __half smh[];
    __half* sAh = smh;                       // [2][A_TILE]
    __half* sAl = sAh + 2 * A_TILE;
    __half* sBh = sAl + 2 * A_TILE;          // [2][B_TILE]
    __half* sBl = sBh + 2 * B_TILE;
    float* ssc = (float*)(sBl + 2 * B_TILE);
    float* sbi = ssc + 192;

    const int tid = threadIdx.x;
    const int h = blockIdx.x, b = blockIdx.y;

    if (tid < 192) {
        float scv = gamma[tid] * rsqrtf(var[tid] + 1e-4f);
        ssc[tid] = scv;
        sbi[tid] = (bm[tid] - mean[tid]) * scv + beta[tid];
    }

    const int lane = tid & 31;
    const int wid = tid >> 5;
    const int wm = wid & 1;          // 2 M-groups of 96
    const int wn = wid >> 1;         // 4 N-groups of 32
    const int lr = lane >> 2;        // fragment row 0..7
    const int lc2 = (lane & 3) * 2;  // fragment col pair
    const int grp = lane >> 3;       // ldmatrix address group
    const int gr  = lane & 7;
    // ldmatrix per-lane offsets (in halfs) relative to (tile_row, tile_col)
    const int aoff = ((grp & 1) * 8 + gr) * AST + (grp >> 1) * 8;
    const int boff = ((grp >> 1) * 8 + gr) * AST + (grp & 1) * 8;

    float acc[6][4][4];
#pragma unroll
    for (int mt = 0; mt < 6; mt++)
#pragma unroll
        for (int nt = 0; nt < 4; nt++)
#pragma unroll
            for (int i = 0; i < 4; i++) acc[mt][nt][i] = 0.f;

    auto stage = [&](int kc, int buf) {
        const int tap = kc / 6;
        const int ch0 = (kc - tap * 6) * 32;
        const int dh = tap / 3 - 1;
        const int dw = tap - (tap / 3) * 3 - 1;
        const int row = h + dh;
        const bool rok = ((unsigned)row < 128u);
        const __half* wh = g_wh16 + (size_t)kc * 6144;
        const __half* wl = g_wl16 + (size_t)kc * 6144;
#pragma unroll
        for (int i = 0; i < 3; i++) {
            int idx = tid + i * 256;          // 0..767
            int r = idx >> 2, g = idx & 3;
            cpa16(sAh + buf * A_TILE + r * AST + g * 8, wh + r * 32 + g * 8);
            cpa16(sAl + buf * A_TILE + r * AST + g * 8, wl + r * 32 + g * 8);
        }
        const size_t rowbase = ((size_t)(b * 128 + row) * 128) * 192;
#pragma unroll
        for (int i = 0; i < 2; i++) {
            int idx = tid + i * 256;          // 0..511
            int r = idx >> 2, g = idx & 3;
            int wsrc = r + dw;
            bool ok = rok && ((unsigned)wsrc < 128u);
            __half* dh_ = sBh + buf * B_TILE + r * AST + g * 8;
            __half* dl_ = sBl + buf * B_TILE + r * AST + g * 8;
            if (ok) {
                size_t sidx = rowbase + (size_t)wsrc * 192 + ch0 + g * 8;
                cpa16(dh_, g_inh + sidx);
                cpa16(dl_, g_inl + sidx);
            } else {
                *(uint4*)dh_ = make_uint4(0, 0, 0, 0);
                *(uint4*)dl_ = make_uint4(0, 0, 0, 0);
            }
        }
    };

    stage(0, 0);
    CP_COMMIT();

    for (int kc = 0; kc < 54; kc++) {
        const int buf = kc & 1;
        if (kc < 53) stage(kc + 1, (kc + 1) & 1);
        CP_COMMIT();
        CP_WAIT1();
        __syncthreads();

        const __half* bAh = sAh + buf * A_TILE;
        const __half* bAl = sAl + buf * A_TILE;
        const __half* bBh = sBh + buf * B_TILE;
        const __half* bBl = sBl + buf * B_TILE;

#pragma unroll
        for (int ks = 0; ks < 2; ks++) {
            const int kk = ks * 16;
            uint32_t bh[4][2], bl[4][2];
#pragma unroll
            for (int ntp = 0; ntp < 2; ntp++) {
                const int nb = (wn * 32 + ntp * 16) * AST + kk + boff;
                ldsm4(bh[ntp * 2][0], bh[ntp * 2][1], bh[ntp * 2 + 1][0],
                      bh[ntp * 2 + 1][1], bBh + nb);
                ldsm4(bl[ntp * 2][0], bl[ntp * 2][1], bl[ntp * 2 + 1][0],
                      bl[ntp * 2 + 1][1], bBl + nb);
            }
#pragma unroll
            for (int mt = 0; mt < 6; mt++) {
                const int mb = (wm * 96 + mt * 16) * AST + kk + aoff;
                uint32_t ah0, ah1, ah2, ah3, al0, al1, al2, al3;
                ldsm4(ah0, ah1, ah2, ah3, bAh + mb);
                ldsm4(al0, al1, al2, al3, bAl + mb);
#pragma unroll
                for (int nt = 0; nt < 4; nt++)
                    mma16816(acc[mt][nt], ah0, ah1, ah2, ah3, bh[nt][0], bh[nt][1]);
#pragma unroll
                for (int nt = 0; nt < 4; nt++)
                    mma16816(acc[mt][nt], al0, al1, al2, al3, bh[nt][0], bh[nt][1]);
#pragma unroll
                for (int nt = 0; nt < 4; nt++)
                    mma16816(acc[mt][nt], ah0, ah1, ah2, ah3, bl[nt][0], bl[nt][1]);
            }
        }
        __syncthreads();
    }

    // Epilogue: BN + ReLU, direct stores (float2 per fragment row)
#pragma unroll
    for (int mt = 0; mt < 6; mt++) {
        int o0 = wm * 96 + mt * 16 + lr;
        float s0 = ssc[o0],     bi0 = sbi[o0];
        float s1 = ssc[o0 + 8], bi1 = sbi[o0 + 8];
#pragma unroll
        for (int nt = 0; nt < 4; nt++) {
            int wcol = wn * 32 + nt * 8 + lc2;
            float2 v0, v1;
            v0.x = fmaxf(acc[mt][nt][0] * s0 + bi0, 0.f);
            v0.y = fmaxf(acc[mt][nt][1] * s0 + bi0, 0.f);
            v1.x = fmaxf(acc[mt][nt][2] * s1 + bi1, 0.f);
            v1.y = fmaxf(acc[mt][nt][3] * s1 + bi1, 0.f);
            size_t p0 = (((size_t)b * C3 + o0)     * H + h) * W + wcol;
            size_t p1 = (((size_t)b * C3 + o0 + 8) * H + h) * W + wcol;
            *(float2*)(out + p0) = v0;
            *(float2*)(out + p1) = v1;
        }
    }
}

// ---------------------------------------------------------------------------

extern "C" void kernel_launch(void* const* d_in, const int* in_sizes, int n_in,
                              void* d_out, int out_size) {
    const float* x    = (const float*)d_in[0];
    const float* xf   = (const float*)d_in[1];
    const float* xr   = (const float*)d_in[2];
    const float* Wx   = (const float*)d_in[3];
    const float* bx   = (const float*)d_in[4];
    const float* Wx1  = (const float*)d_in[5];
    const float* bx1  = (const float*)d_in[6];
    const float* Wx2  = (const float*)d_in[7];
    const float* bx2  = (const float*)d_in[8];
    const float* Wxf  = (const float*)d_in[9];
    const float* bxf  = (const float*)d_in[10];
    const float* Wxr  = (const float*)d_in[11];
    const float* bxr  = (const float*)d_in[12];
    const float* Wm   = (const float*)d_in[13];
    const float* bm   = (const float*)d_in[14];
    const float* gam  = (const float*)d_in[15];
    const float* bet  = (const float*)d_in[16];
    const float* mean = (const float*)d_in[17];
    const float* var  = (const float*)d_in[18];
    float* out = (float*)d_out;

    const int proj_smem = PROJ_SMEM_FLOATS * 4;
    const int attn_smem = ATTN_SMEM_FLOATS * 4;
    const int inprep_smem = INPREP_SMEM_FLOATS * 4;
    const int conv_smem = CONV_SMEM_BYTES;
    cudaFuncSetAttribute(proj_kernel, cudaFuncAttributeMaxDynamicSharedMemorySize, proj_smem);
    cudaFuncSetAttribute(attn_kernel, cudaFuncAttributeMaxDynamicSharedMemorySize, attn_smem);
    cudaFuncSetAttribute(inprep_kernel, cudaFuncAttributeMaxDynamicSharedMemorySize, inprep_smem);
    cudaFuncSetAttribute(conv_mma_kernel, cudaFuncAttributeMaxDynamicSharedMemorySize, conv_smem);

    proj_kernel<<<B * HW / 128, 256, proj_smem>>>(x, xf, xr, Wx, bx, Wx1, bx1,
                                                  Wx2, bx2, Wxf, bxf, Wxr, bxr);
    wprep_kernel<<<54, 192>>>(Wm);
    attn_kernel<<<dim3(H, B), 256, attn_smem>>>();
    inprep_kernel<<<dim3(H, B), 256, inprep_smem>>>(x);
    conv_mma_kernel<<<dim3(H, B), 256, conv_smem>>>(bm, gam, bet, mean, var, out);
}

// round 5
// speedup vs baseline: 3.5663x; 1.0964x over previous
#include <cuda_runtime.h>
#include <cuda_fp16.h>
#include <cstdint>

// Problem constants
constexpr int C   = 64;
constexpr int H   = 128;
constexpr int W   = 128;
constexpr int HW  = H * W;          // 16384
constexpr int B   = 8;
constexpr int C3  = 192;

// ---------------------------------------------------------------------------
// Scratch (device globals). All intermediates are split fp16 (hi + lo).
// ---------------------------------------------------------------------------
// [b][h][c][w] layouts for attention GEMM1 operands
__device__ __half g_x1h[(size_t)B * H * C * W], g_x1l[(size_t)B * H * C * W];
__device__ __half g_x2h[(size_t)B * H * C * W], g_x2l[(size_t)B * H * C * W];
__device__ __half g_xfh[(size_t)B * H * C * W], g_xfl[(size_t)B * H * C * W];
__device__ __half g_xrh[(size_t)B * H * C * W], g_xrl[(size_t)B * H * C * W];
// xp transposed [b][h][w][c] for attention GEMM2 B operand
__device__ __half g_xpth[(size_t)B * H * W * C], g_xptl[(size_t)B * H * W * C];
// conv input, channel-last [b][h][w][192]
__device__ __half g_inh[(size_t)B * H * W * C3];
__device__ __half g_inl[(size_t)B * H * W * C3];
// conv weights, chunked [kc][o][32]
__device__ __half g_wh16[54 * 192 * 32];
__device__ __half g_wl16[54 * 192 * 32];

// ---------------------------------------------------------------------------
// Helpers
// ---------------------------------------------------------------------------
__device__ __forceinline__ void cpa16(void* dst, const void* src) {
    uint32_t d = (uint32_t)__cvta_generic_to_shared(dst);
    asm volatile("cp.async.cg.shared.global [%0], [%1], 16;" :: "r"(d), "l"(src));
}
#define CP_COMMIT() asm volatile("cp.async.commit_group;" ::: "memory")
#define CP_WAIT1()  asm volatile("cp.async.wait_group 1;" ::: "memory")

__device__ __forceinline__ void mma16816(float acc[4], uint32_t a0, uint32_t a1,
                                         uint32_t a2, uint32_t a3,
                                         uint32_t b0, uint32_t b1) {
    asm volatile(
        "mma.sync.aligned.m16n8k16.row.col.f32.f16.f16.f32 "
        "{%0,%1,%2,%3}, {%4,%5,%6,%7}, {%8,%9}, {%0,%1,%2,%3};"
        : "+f"(acc[0]), "+f"(acc[1]), "+f"(acc[2]), "+f"(acc[3])
        : "r"(a0), "r"(a1), "r"(a2), "r"(a3), "r"(b0), "r"(b1));
}

__device__ __forceinline__ void ldsm4(uint32_t& r0, uint32_t& r1, uint32_t& r2,
                                      uint32_t& r3, const __half* p) {
    uint32_t a = (uint32_t)__cvta_generic_to_shared(p);
    asm volatile("ldmatrix.sync.aligned.m8n8.x4.shared.b16 {%0,%1,%2,%3}, [%4];"
                 : "=r"(r0), "=r"(r1), "=r"(r2), "=r"(r3) : "r"(a));
}

__device__ __forceinline__ void split16(float v, __half& hi, __half& lo) {
    hi = __float2half_rn(v);
    lo = __float2half_rn(v - __half2float(hi));
}

// ---------------------------------------------------------------------------
// Kernel 1: pointwise projections (fp32 register GEMM), outputs split fp16.
// One block per (b,h) row (128 positions). 2 CTAs/SM.
// ---------------------------------------------------------------------------

#define WIDX(o, c) (((c) << 6) | ((o) ^ ((c) & 31)))
#define PROJ_SMEM_FLOATS (5 * 4096 + 64 * 128)

__device__ __forceinline__ void proj_gemm(const float* __restrict__ sW,
                                          const float* __restrict__ sIn,
                                          float acc[4][8], int o0, int wg) {
#pragma unroll
    for (int j = 0; j < 4; j++)
#pragma unroll
        for (int i = 0; i < 8; i++) acc[j][i] = 0.f;
    for (int c = 0; c < 64; c++) {
        float in[8];
#pragma unroll
        for (int i = 0; i < 8; i++) in[i] = sIn[c * 128 + wg + 16 * i];
        float wv[4];
#pragma unroll
        for (int j = 0; j < 4; j++) wv[j] = sW[WIDX(o0 + j, c)];
#pragma unroll
        for (int j = 0; j < 4; j++)
#pragma unroll
            for (int i = 0; i < 8; i++) acc[j][i] += wv[j] * in[i];
    }
}

// store acc (+bias) as split fp16 in [c][w] layout
__device__ __forceinline__ void store_cw(float acc[4][8], const float* bias,
                                         __half* dh, __half* dl,
                                         size_t bh, int o0, int wg) {
#pragma unroll
    for (int j = 0; j < 4; j++) {
        float bb = __ldg(bias + o0 + j);
        size_t rb = (bh * 64 + o0 + j) * 128;
#pragma unroll
        for (int i = 0; i < 8; i++) {
            __half hi, lo;
            split16(acc[j][i] + bb, hi, lo);
            dh[rb + wg + 16 * i] = hi;
            dl[rb + wg + 16 * i] = lo;
        }
    }
}

__global__ __launch_bounds__(256, 2) void proj_kernel(
    const float* __restrict__ x, const float* __restrict__ xf, const float* __restrict__ xr,
    const float* __restrict__ Wx,  const float* __restrict__ bx,
    const float* __restrict__ Wx1, const float* __restrict__ bx1,
    const float* __restrict__ Wx2, const float* __restrict__ bx2,
    const float* __restrict__ Wxf, const float* __restrict__ bxf,
    const float* __restrict__ Wxr, const float* __restrict__ bxr) {
    extern __shared__ float sm[];
    float* sWx  = sm;
    float* sWx1 = sWx  + 4096;
    float* sWx2 = sWx1 + 4096;
    float* sWxf = sWx2 + 4096;
    float* sWxr = sWxf + 4096;
    float* sIn  = sWxr + 4096;   // [64][128], reused for x / xp / xf / xr

    const int tid = threadIdx.x;
    const int b   = blockIdx.x >> 7;
    const int h   = blockIdx.x & 127;
    const size_t bh = (size_t)b * 128 + h;
    const size_t gbase = (size_t)b * C * HW + (size_t)h * W;

    for (int i = tid; i < 4096; i += 256) {
        int o = i >> 6, c = i & 63;
        int s = WIDX(o, c);
        sWx [s] = Wx [i];
        sWx1[s] = Wx1[i];
        sWx2[s] = Wx2[i];
        sWxf[s] = Wxf[i];
        sWxr[s] = Wxr[i];
    }
    for (int i = tid; i < 8192; i += 256) {
        int c = i >> 7, p = i & 127;
        sIn[i] = x[gbase + (size_t)c * HW + p];
    }
    __syncthreads();

    const int og = tid >> 4;
    const int wg = tid & 15;
    const int o0 = og * 4;
    float acc[4][8];

    // xp -> smem tile (aliased) + transposed split fp16 global
    proj_gemm(sWx, sIn, acc, o0, wg);
    __syncthreads();                 // everyone done reading x
#pragma unroll
    for (int j = 0; j < 4; j++) {
        float bb = __ldg(bx + o0 + j);
#pragma unroll
        for (int i = 0; i < 8; i++) acc[j][i] += bb;
    }
#pragma unroll
    for (int i = 0; i < 8; i++) {
        int p = wg + 16 * i;
        __half hi0, lo0, hi1, lo1, hi2, lo2, hi3, lo3;
        split16(acc[0][i], hi0, lo0);
        split16(acc[1][i], hi1, lo1);
        split16(acc[2][i], hi2, lo2);
        split16(acc[3][i], hi3, lo3);
#pragma unroll
        for (int j = 0; j < 4; j++) sIn[(o0 + j) * 128 + p] = acc[j][i];
        size_t wb = (bh * 128 + p) * 64 + o0;
        __half2 ph0 = __halves2half2(hi0, hi1), ph1 = __halves2half2(hi2, hi3);
        __half2 pl0 = __halves2half2(lo0, lo1), pl1 = __halves2half2(lo2, lo3);
        *(__half2*)(g_xpth + wb)     = ph0;
        *(__half2*)(g_xpth + wb + 2) = ph1;
        *(__half2*)(g_xptl + wb)     = pl0;
        *(__half2*)(g_xptl + wb + 2) = pl1;
    }
    __syncthreads();

    // x1, x2 (projections of xp)
    proj_gemm(sWx1, sIn, acc, o0, wg);
    store_cw(acc, bx1, g_x1h, g_x1l, bh, o0, wg);
    proj_gemm(sWx2, sIn, acc, o0, wg);
    __syncthreads();                 // done reading xp tile
    store_cw(acc, bx2, g_x2h, g_x2l, bh, o0, wg);

    // xfp
    for (int i = tid; i < 8192; i += 256) {
        int c = i >> 7, p = i & 127;
        sIn[i] = xf[gbase + (size_t)c * HW + p];
    }
    __syncthreads();
    proj_gemm(sWxf, sIn, acc, o0, wg);
    __syncthreads();
    store_cw(acc, bxf, g_xfh, g_xfl, bh, o0, wg);

    // xrp
    for (int i = tid; i < 8192; i += 256) {
        int c = i >> 7, p = i & 127;
        sIn[i] = xr[gbase + (size_t)c * HW + p];
    }
    __syncthreads();
    proj_gemm(sWxr, sIn, acc, o0, wg);
    store_cw(acc, bxr, g_xrh, g_xrl, bh, o0, wg);
}

// ---------------------------------------------------------------------------
// Kernel 2: tensor-core attention + conv-input packing (inprep fused in).
// One CTA per (b,h), 256 threads, 2 CTAs/SM.
// GEMM1: score[64][64] = x1 @ xfp^T  (K=128 over w), 3-term fp16 split.
// GEMM2: feat[64][128] = score @ xp  (K=64 over d), 3-term fp16 split.
// feat packed channel-last split-fp16 into g_inh/g_inl (channels pass*64..).
// x itself packed into channels 128..191.
// ---------------------------------------------------------------------------

#define AS1 136   // [64][w] tile stride (halfs)  -> 272B rows (conflict-free)
#define ASP 72    // xpt [128][d] tile stride     -> 144B rows (conflict-free)
#define ASS 72    // score [64][d] stride
#define ASF 129   // feat fp32 staging stride (floats)
// half-index offsets in dynamic smem
#define O_X1H 0
#define O_X1L 8704
#define O_XFH 17408
#define O_XFL 26112
#define O_PH  34816
#define O_PL  44032
#define ATTN_SMEM_HALFS 53248   // 106496 bytes

__global__ __launch_bounds__(256, 2) void attn_mma_kernel(const float* __restrict__ x) {
    extern __shared__ __align__(16) __half smh[];
    __half* sX1h = smh + O_X1H;
    __half* sX1l = smh + O_X1L;
    __half* sXfh = smh + O_XFH;
    __half* sXfl = smh + O_XFL;
    __half* sPh  = smh + O_PH;
    __half* sPl  = smh + O_PL;
    __half* sSh  = smh + O_XFH;            // alias over sXf after GEMM1
    __half* sSl  = smh + O_XFH + 4608;
    float*  sF   = (float*)smh;            // alias over sX1 (8256 floats)

    const int tid = threadIdx.x;
    const int h = blockIdx.x, b = blockIdx.y;
    const size_t bh = (size_t)b * 128 + h;

    const int lane = tid & 31;
    const int wid = tid >> 5;
    const int lr = lane >> 2;
    const int lc2 = (lane & 3) * 2;
    const int grp = lane >> 3;
    const int gr  = lane & 7;

    uint32_t* outh = (uint32_t*)g_inh;
    uint32_t* outl = (uint32_t*)g_inl;
    const size_t wbase = bh * 128 * 96;    // uint32 words per (b,h): 128 w x 96

    // ---- load xpt (both passes use it) ----
    {
        const __half* srcH = g_xpth + bh * 128 * 64;
        const __half* srcL = g_xptl + bh * 128 * 64;
        for (int idx = tid; idx < 1024; idx += 256) {   // 128 rows x 8 x 16B
            int r = idx >> 3, g = idx & 7;
            *(uint4*)(sPh + r * ASP + g * 8) = *(const uint4*)(srcH + r * 64 + g * 8);
            *(uint4*)(sPl + r * ASP + g * 8) = *(const uint4*)(srcL + r * 64 + g * 8);
        }
    }
    // ---- pack x (channels 128..191) via smem transpose ----
    {
        const size_t xbase = (size_t)b * C * HW + (size_t)h * W;
        for (int idx = tid; idx < 8192; idx += 256) {
            int c = idx >> 7, w = idx & 127;
            sF[c * ASF + w] = x[xbase + (size_t)c * HW + w];
        }
        __syncthreads();
        for (int idx = tid; idx < 4096; idx += 256) {
            int q = idx & 31, w = idx >> 5;
            int c = q * 2;
            __half h0, l0, h1, l1;
            split16(sF[c * ASF + w], h0, l0);
            split16(sF[(c + 1) * ASF + w], h1, l1);
            __half2 ph = __halves2half2(h0, h1);
            __half2 pl = __halves2half2(l0, l1);
            outh[wbase + (size_t)w * 96 + 64 + q] = *(uint32_t*)&ph;
            outl[wbase + (size_t)w * 96 + 64 + q] = *(uint32_t*)&pl;
        }
    }

    const int aoff1 = ((grp & 1) * 8 + gr) * AS1 + (grp >> 1) * 8;
    const int boff1 = ((grp >> 1) * 8 + gr) * AS1 + (grp & 1) * 8;
    const int aoffS = ((grp & 1) * 8 + gr) * ASS + (grp >> 1) * 8;
    const int boffP = ((grp >> 1) * 8 + gr) * ASP + (grp & 1) * 8;

    for (int pass = 0; pass < 2; pass++) {
        const __half* gAh = pass ? g_x2h : g_x1h;
        const __half* gAl = pass ? g_x2l : g_x1l;
        const __half* gBh = pass ? g_xrh : g_xfh;
        const __half* gBl = pass ? g_xrl : g_xfl;

        __syncthreads();   // previous pack / x-pack done before overwriting
        {
            const size_t sb = bh * 64 * 128;
            for (int idx = tid; idx < 1024; idx += 256) {  // 64 rows x 16 x 16B
                int r = idx >> 4, g = idx & 15;
                *(uint4*)(sX1h + r * AS1 + g * 8) = *(const uint4*)(gAh + sb + r * 128 + g * 8);
                *(uint4*)(sX1l + r * AS1 + g * 8) = *(const uint4*)(gAl + sb + r * 128 + g * 8);
                *(uint4*)(sXfh + r * AS1 + g * 8) = *(const uint4*)(gBh + sb + r * 128 + g * 8);
                *(uint4*)(sXfl + r * AS1 + g * 8) = *(const uint4*)(gBl + sb + r * 128 + g * 8);
            }
        }
        __syncthreads();

        // ---- GEMM1: score = x1 @ xfp^T, warps 4(M)x2(N) ----
        float sacc[4][4];
#pragma unroll
        for (int nf = 0; nf < 4; nf++)
#pragma unroll
            for (int i = 0; i < 4; i++) sacc[nf][i] = 0.f;
        {
            const int m0 = (wid & 3) * 16, n0 = (wid >> 2) * 32;
#pragma unroll
            for (int ks = 0; ks < 8; ks++) {
                const int k0 = ks * 16;
                uint32_t bhf[4][2], blf[4][2];
#pragma unroll
                for (int ntp = 0; ntp < 2; ntp++) {
                    const int nb = (n0 + ntp * 16) * AS1 + k0 + boff1;
                    ldsm4(bhf[ntp * 2][0], bhf[ntp * 2][1], bhf[ntp * 2 + 1][0],
                          bhf[ntp * 2 + 1][1], sXfh + nb);
                    ldsm4(blf[ntp * 2][0], blf[ntp * 2][1], blf[ntp * 2 + 1][0],
                          blf[ntp * 2 + 1][1], sXfl + nb);
                }
                const int mb = m0 * AS1 + k0 + aoff1;
                uint32_t ah0, ah1, ah2, ah3, al0, al1, al2, al3;
                ldsm4(ah0, ah1, ah2, ah3, sX1h + mb);
                ldsm4(al0, al1, al2, al3, sX1l + mb);
#pragma unroll
                for (int nf = 0; nf < 4; nf++)
                    mma16816(sacc[nf], ah0, ah1, ah2, ah3, bhf[nf][0], bhf[nf][1]);
#pragma unroll
                for (int nf = 0; nf < 4; nf++)
                    mma16816(sacc[nf], al0, al1, al2, al3, bhf[nf][0], bhf[nf][1]);
#pragma unroll
                for (int nf = 0; nf < 4; nf++)
                    mma16816(sacc[nf], ah0, ah1, ah2, ah3, blf[nf][0], blf[nf][1]);
            }
        }
        __syncthreads();   // all warps done reading sXf -> safe to alias score

        // ---- score -> smem split fp16 ----
        {
            const int m0 = (wid & 3) * 16, n0 = (wid >> 2) * 32;
#pragma unroll
            for (int nf = 0; nf < 4; nf++)
#pragma unroll
                for (int i = 0; i < 4; i++) {
                    int row = m0 + lr + (i >= 2 ? 8 : 0);
                    int col = n0 + nf * 8 + lc2 + (i & 1);
                    __half hi, lo;
                    split16(sacc[nf][i], hi, lo);
                    sSh[row * ASS + col] = hi;
                    sSl[row * ASS + col] = lo;
                }
        }
        __syncthreads();

        // ---- GEMM2: feat = score @ xp, warps 2(M)x4(N) ----
        float facc[2][4][4];
#pragma unroll
        for (int mt = 0; mt < 2; mt++)
#pragma unroll
            for (int nf = 0; nf < 4; nf++)
#pragma unroll
                for (int i = 0; i < 4; i++) facc[mt][nf][i] = 0.f;
        {
            const int m0 = (wid & 1) * 32, n0 = (wid >> 1) * 32;
#pragma unroll
            for (int ks = 0; ks < 4; ks++) {
                const int k0 = ks * 16;
                uint32_t bhf[4][2], blf[4][2];
#pragma unroll
                for (int ntp = 0; ntp < 2; ntp++) {
                    const int nb = (n0 + ntp * 16) * ASP + k0 + boffP;
                    ldsm4(bhf[ntp * 2][0], bhf[ntp * 2][1], bhf[ntp * 2 + 1][0],
                          bhf[ntp * 2 + 1][1], sPh + nb);
                    ldsm4(blf[ntp * 2][0], blf[ntp * 2][1], blf[ntp * 2 + 1][0],
                          blf[ntp * 2 + 1][1], sPl + nb);
                }
#pragma unroll
                for (int mt = 0; mt < 2; mt++) {
                    const int mb = (m0 + mt * 16) * ASS + k0 + aoffS;
                    uint32_t ah0, ah1, ah2, ah3, al0, al1, al2, al3;
                    ldsm4(ah0, ah1, ah2, ah3, sSh + mb);
                    ldsm4(al0, al1, al2, al3, sSl + mb);
#pragma unroll
                    for (int nf = 0; nf < 4; nf++)
                        mma16816(facc[mt][nf], ah0, ah1, ah2, ah3, bhf[nf][0], bhf[nf][1]);
#pragma unroll
                    for (int nf = 0; nf < 4; nf++)
                        mma16816(facc[mt][nf], al0, al1, al2, al3, bhf[nf][0], bhf[nf][1]);
#pragma unroll
                    for (int nf = 0; nf < 4; nf++)
                        mma16816(facc[mt][nf], ah0, ah1, ah2, ah3, blf[nf][0], blf[nf][1]);
                }
            }
        }
        // write feat fp32 into sF (aliases sX1; GEMM2 readers touch only sS/sP)
        {
            const int m0 = (wid & 1) * 32, n0 = (wid >> 1) * 32;
#pragma unroll
            for (int mt = 0; mt < 2; mt++)
#pragma unroll
                for (int nf = 0; nf < 4; nf++)
#pragma unroll
                    for (int i = 0; i < 4; i++) {
                        int row = m0 + mt * 16 + lr + (i >= 2 ? 8 : 0);
                        int col = n0 + nf * 8 + lc2 + (i & 1);
                        sF[row * ASF + col] = facc[mt][nf][i];
                    }
        }
        __syncthreads();

        // ---- pack feat into conv input (channels pass*64 .. pass*64+63) ----
        for (int idx = tid; idx < 4096; idx += 256) {
            int q = idx & 31, w = idx >> 5;
            int c = q * 2;
            __half h0, l0, h1, l1;
            split16(sF[c * ASF + w], h0, l0);
            split16(sF[(c + 1) * ASF + w], h1, l1);
            __half2 ph = __halves2half2(h0, h1);
            __half2 pl = __halves2half2(l0, l1);
            outh[wbase + (size_t)w * 96 + pass * 32 + q] = *(uint32_t*)&ph;
            outl[wbase + (size_t)w * 96 + pass * 32 + q] = *(uint32_t*)&pl;
        }
    }
}

// ---------------------------------------------------------------------------
// Kernel 3a: weight prep (unchanged).
// ---------------------------------------------------------------------------
__global__ void wprep_kernel(const float* __restrict__ Wm) {
    const int kc = blockIdx.x;       // 0..53
    const int o  = threadIdx.x;      // 0..191
    const int tap = kc / 6;
    const int ch0 = (kc - tap * 6) * 32;
#pragma unroll
    for (int j = 0; j < 32; j++) {
        float v  = Wm[((size_t)o * 192 + ch0 + j) * 9 + tap];
        __half hi, lo;
        split16(v, hi, lo);
        size_t d = ((size_t)kc * 192 + o) * 32 + j;
        g_wh16[d] = hi;
        g_wl16[d] = lo;
    }
}

// ---------------------------------------------------------------------------
// Kernel 3b: fp16 split mma.sync implicit-GEMM conv + BN + ReLU (unchanged).
// ---------------------------------------------------------------------------

#define AST 40
#define A_TILE (192 * AST)
#define B_TILE (128 * AST)
#define CONV_SMEM_BYTES ((2 * A_TILE * 2 + 2 * B_TILE * 2) * 2 + 384 * 4)

__global__ __launch_bounds__(256, 2) void conv_mma_kernel(
    const float* __restrict__ bm, const float* __restrict__ gamma,
    const float* __restrict__ beta, const float* __restrict__ mean,
    const float* __restrict__ var, float* __restrict__ out) {
    extern __shared__ __align__(16) __half smh[];
    __half* sAh = smh;
    __half* sAl = sAh + 2 * A_TILE;
    __half* sBh = sAl + 2 * A_TILE;
    __half* sBl = sBh + 2 * B_TILE;
    float* ssc = (float*)(sBl + 2 * B_TILE);
    float* sbi = ssc + 192;

    const int tid = threadIdx.x;
    const int h = blockIdx.x, b = blockIdx.y;

    if (tid < 192) {
        float scv = gamma[tid] * rsqrtf(var[tid] + 1e-4f);
        ssc[tid] = scv;
        sbi[tid] = (bm[tid] - mean[tid]) * scv + beta[tid];
    }

    const int lane = tid & 31;
    const int wid = tid >> 5;
    const int wm = wid & 1;
    const int wn = wid >> 1;
    const int lr = lane >> 2;
    const int lc2 = (lane & 3) * 2;
    const int grp = lane >> 3;
    const int gr  = lane & 7;
    const int aoff = ((grp & 1) * 8 + gr) * AST + (grp >> 1) * 8;
    const int boff = ((grp >> 1) * 8 + gr) * AST + (grp & 1) * 8;

    float acc[6][4][4];
#pragma unroll
    for (int mt = 0; mt < 6; mt++)
#pragma unroll
        for (int nt = 0; nt < 4; nt++)
#pragma unroll
            for (int i = 0; i < 4; i++) acc[mt][nt][i] = 0.f;

    auto stage = [&](int kc, int buf) {
        const int tap = kc / 6;
        const int ch0 = (kc - tap * 6) * 32;
        const int dh = tap / 3 - 1;
        const int dw = tap - (tap / 3) * 3 - 1;
        const int row = h + dh;
        const bool rok = ((unsigned)row < 128u);
        const __half* wh = g_wh16 + (size_t)kc * 6144;
        const __half* wl = g_wl16 + (size_t)kc * 6144;
#pragma unroll
        for (int i = 0; i < 3; i++) {
            int idx = tid + i * 256;
            int r = idx >> 2, g = idx & 3;
            cpa16(sAh + buf * A_TILE + r * AST + g * 8, wh + r * 32 + g * 8);
            cpa16(sAl + buf * A_TILE + r * AST + g * 8, wl + r * 32 + g * 8);
        }
        const size_t rowbase = ((size_t)(b * 128 + row) * 128) * 192;
#pragma unroll
        for (int i = 0; i < 2; i++) {
            int idx = tid + i * 256;
            int r = idx >> 2, g = idx & 3;
            int wsrc = r + dw;
            bool ok = rok && ((unsigned)wsrc < 128u);
            __half* dh_ = sBh + buf * B_TILE + r * AST + g * 8;
            __half* dl_ = sBl + buf * B_TILE + r * AST + g * 8;
            if (ok) {
                size_t sidx = rowbase + (size_t)wsrc * 192 + ch0 + g * 8;
                cpa16(dh_, g_inh + sidx);
                cpa16(dl_, g_inl + sidx);
            } else {
                *(uint4*)dh_ = make_uint4(0, 0, 0, 0);
                *(uint4*)dl_ = make_uint4(0, 0, 0, 0);
            }
        }
    };

    stage(0, 0);
    CP_COMMIT();

    for (int kc = 0; kc < 54; kc++) {
        const int buf = kc & 1;
        if (kc < 53) stage(kc + 1, (kc + 1) & 1);
        CP_COMMIT();
        CP_WAIT1();
        __syncthreads();

        const __half* bAh = sAh + buf * A_TILE;
        const __half* bAl = sAl + buf * A_TILE;
        const __half* bBh = sBh + buf * B_TILE;
        const __half* bBl = sBl + buf * B_TILE;

#pragma unroll
        for (int ks = 0; ks < 2; ks++) {
            const int kk = ks * 16;
            uint32_t bh[4][2], bl[4][2];
#pragma unroll
            for (int ntp = 0; ntp < 2; ntp++) {
                const int nb = (wn * 32 + ntp * 16) * AST + kk + boff;
                ldsm4(bh[ntp * 2][0], bh[ntp * 2][1], bh[ntp * 2 + 1][0],
                      bh[ntp * 2 + 1][1], bBh + nb);
                ldsm4(bl[ntp * 2][0], bl[ntp * 2][1], bl[ntp * 2 + 1][0],
                      bl[ntp * 2 + 1][1], bBl + nb);
            }
#pragma unroll
            for (int mt = 0; mt < 6; mt++) {
                const int mb = (wm * 96 + mt * 16) * AST + kk + aoff;
                uint32_t ah0, ah1, ah2, ah3, al0, al1, al2, al3;
                ldsm4(ah0, ah1, ah2, ah3, bAh + mb);
                ldsm4(al0, al1, al2, al3, bAl + mb);
#pragma unroll
                for (int nt = 0; nt < 4; nt++)
                    mma16816(acc[mt][nt], ah0, ah1, ah2, ah3, bh[nt][0], bh[nt][1]);
#pragma unroll
                for (int nt = 0; nt < 4; nt++)
                    mma16816(acc[mt][nt], al0, al1, al2, al3, bh[nt][0], bh[nt][1]);
#pragma unroll
                for (int nt = 0; nt < 4; nt++)
                    mma16816(acc[mt][nt], ah0, ah1, ah2, ah3, bl[nt][0], bl[nt][1]);
            }
        }
        __syncthreads();
    }

#pragma unroll
    for (int mt = 0; mt < 6; mt++) {
        int o0 = wm * 96 + mt * 16 + lr;
        float s0 = ssc[o0],     bi0 = sbi[o0];
        float s1 = ssc[o0 + 8], bi1 = sbi[o0 + 8];
#pragma unroll
        for (int nt = 0; nt < 4; nt++) {
            int wcol = wn * 32 + nt * 8 + lc2;
            float2 v0, v1;
            v0.x = fmaxf(acc[mt][nt][0] * s0 + bi0, 0.f);
            v0.y = fmaxf(acc[mt][nt][1] * s0 + bi0, 0.f);
            v1.x = fmaxf(acc[mt][nt][2] * s1 + bi1, 0.f);
            v1.y = fmaxf(acc[mt][nt][3] * s1 + bi1, 0.f);
            size_t p0 = (((size_t)b * C3 + o0)     * H + h) * W + wcol;
            size_t p1 = (((size_t)b * C3 + o0 + 8) * H + h) * W + wcol;
            *(float2*)(out + p0) = v0;
            *(float2*)(out + p1) = v1;
        }
    }
}

// ---------------------------------------------------------------------------

extern "C" void kernel_launch(void* const* d_in, const int* in_sizes, int n_in,
                              void* d_out, int out_size) {
    const float* x    = (const float*)d_in[0];
    const float* xf   = (const float*)d_in[1];
    const float* xr   = (const float*)d_in[2];
    const float* Wx   = (const float*)d_in[3];
    const float* bx   = (const float*)d_in[4];
    const float* Wx1  = (const float*)d_in[5];
    const float* bx1  = (const float*)d_in[6];
    const float* Wx2  = (const float*)d_in[7];
    const float* bx2  = (const float*)d_in[8];
    const float* Wxf  = (const float*)d_in[9];
    const float* bxf  = (const float*)d_in[10];
    const float* Wxr  = (const float*)d_in[11];
    const float* bxr  = (const float*)d_in[12];
    const float* Wm   = (const float*)d_in[13];
    const float* bm   = (const float*)d_in[14];
    const float* gam  = (const float*)d_in[15];
    const float* bet  = (const float*)d_in[16];
    const float* mean = (const float*)d_in[17];
    const float* var  = (const float*)d_in[18];
    float* out = (float*)d_out;

    const int proj_smem = PROJ_SMEM_FLOATS * 4;
    const int attn_smem = ATTN_SMEM_HALFS * 2;
    const int conv_smem = CONV_SMEM_BYTES;
    cudaFuncSetAttribute(proj_kernel, cudaFuncAttributeMaxDynamicSharedMemorySize, proj_smem);
    cudaFuncSetAttribute(attn_mma_kernel, cudaFuncAttributeMaxDynamicSharedMemorySize, attn_smem);
    cudaFuncSetAttribute(conv_mma_kernel, cudaFuncAttributeMaxDynamicSharedMemorySize, conv_smem);

    proj_kernel<<<B * H, 256, proj_smem>>>(x, xf, xr, Wx, bx, Wx1, bx1,
                                           Wx2, bx2, Wxf, bxf, Wxr, bxr);
    wprep_kernel<<<54, 192>>>(Wm);
    attn_mma_kernel<<<dim3(H, B), 256, attn_smem>>>(x);
    conv_mma_kernel<<<dim3(H, B), 256, conv_smem>>>(bm, gam, bet, mean, var, out);
}

// round 6
// speedup vs baseline: 4.4994x; 1.2617x over previous
#include <cuda_runtime.h>
#include <cuda_fp16.h>
#include <cstdint>

// Problem constants
constexpr int C   = 64;
constexpr int H   = 128;
constexpr int W   = 128;
constexpr int HW  = H * W;          // 16384
constexpr int B   = 8;
constexpr int C3  = 192;

// ---------------------------------------------------------------------------
// Scratch (device globals). Intermediates split fp16 (hi + lo).
// ---------------------------------------------------------------------------
__device__ __half g_x1h[(size_t)B * H * C * W], g_x1l[(size_t)B * H * C * W];
__device__ __half g_x2h[(size_t)B * H * C * W], g_x2l[(size_t)B * H * C * W];
__device__ __half g_xfh[(size_t)B * H * C * W], g_xfl[(size_t)B * H * C * W];
__device__ __half g_xrh[(size_t)B * H * C * W], g_xrl[(size_t)B * H * C * W];
__device__ __half g_xpth[(size_t)B * H * W * C], g_xptl[(size_t)B * H * W * C];
// conv input, channel-last [b][h][w][192] — HI ONLY (2-term conv split)
__device__ __half g_inh[(size_t)B * H * W * C3];
// conv weights, chunked [kc][o][32], hi + lo
__device__ __half g_wh16[54 * 192 * 32];
__device__ __half g_wl16[54 * 192 * 32];

// ---------------------------------------------------------------------------
// Helpers
// ---------------------------------------------------------------------------
__device__ __forceinline__ void cpa16(void* dst, const void* src) {
    uint32_t d = (uint32_t)__cvta_generic_to_shared(dst);
    asm volatile("cp.async.cg.shared.global [%0], [%1], 16;" :: "r"(d), "l"(src));
}
#define CP_COMMIT() asm volatile("cp.async.commit_group;" ::: "memory")
#define CP_WAIT1()  asm volatile("cp.async.wait_group 1;" ::: "memory")

__device__ __forceinline__ void mma16816(float acc[4], uint32_t a0, uint32_t a1,
                                         uint32_t a2, uint32_t a3,
                                         uint32_t b0, uint32_t b1) {
    asm volatile(
        "mma.sync.aligned.m16n8k16.row.col.f32.f16.f16.f32 "
        "{%0,%1,%2,%3}, {%4,%5,%6,%7}, {%8,%9}, {%0,%1,%2,%3};"
        : "+f"(acc[0]), "+f"(acc[1]), "+f"(acc[2]), "+f"(acc[3])
        : "r"(a0), "r"(a1), "r"(a2), "r"(a3), "r"(b0), "r"(b1));
}

__device__ __forceinline__ void ldsm4(uint32_t& r0, uint32_t& r1, uint32_t& r2,
                                      uint32_t& r3, const __half* p) {
    uint32_t a = (uint32_t)__cvta_generic_to_shared(p);
    asm volatile("ldmatrix.sync.aligned.m8n8.x4.shared.b16 {%0,%1,%2,%3}, [%4];"
                 : "=r"(r0), "=r"(r1), "=r"(r2), "=r"(r3) : "r"(a));
}

__device__ __forceinline__ void split16(float v, __half& hi, __half& lo) {
    hi = __float2half_rn(v);
    lo = __float2half_rn(v - __half2float(hi));
}

// ---------------------------------------------------------------------------
// Kernel 1: pointwise projections (fp32 register GEMM), outputs split fp16.
// ---------------------------------------------------------------------------

#define WIDX(o, c) (((c) << 6) | ((o) ^ ((c) & 31)))
#define PROJ_SMEM_FLOATS (5 * 4096 + 64 * 128)

__device__ __forceinline__ void proj_gemm(const float* __restrict__ sW,
                                          const float* __restrict__ sIn,
                                          float acc[4][8], int o0, int wg) {
#pragma unroll
    for (int j = 0; j < 4; j++)
#pragma unroll
        for (int i = 0; i < 8; i++) acc[j][i] = 0.f;
    for (int c = 0; c < 64; c++) {
        float in[8];
#pragma unroll
        for (int i = 0; i < 8; i++) in[i] = sIn[c * 128 + wg + 16 * i];
        float wv[4];
#pragma unroll
        for (int j = 0; j < 4; j++) wv[j] = sW[WIDX(o0 + j, c)];
#pragma unroll
        for (int j = 0; j < 4; j++)
#pragma unroll
            for (int i = 0; i < 8; i++) acc[j][i] += wv[j] * in[i];
    }
}

__device__ __forceinline__ void store_cw(float acc[4][8], const float* bias,
                                         __half* dh, __half* dl,
                                         size_t bh, int o0, int wg) {
#pragma unroll
    for (int j = 0; j < 4; j++) {
        float bb = __ldg(bias + o0 + j);
        size_t rb = (bh * 64 + o0 + j) * 128;
#pragma unroll
        for (int i = 0; i < 8; i++) {
            __half hi, lo;
            split16(acc[j][i] + bb, hi, lo);
            dh[rb + wg + 16 * i] = hi;
            dl[rb + wg + 16 * i] = lo;
        }
    }
}

__global__ __launch_bounds__(256, 2) void proj_kernel(
    const float* __restrict__ x, const float* __restrict__ xf, const float* __restrict__ xr,
    const float* __restrict__ Wx,  const float* __restrict__ bx,
    const float* __restrict__ Wx1, const float* __restrict__ bx1,
    const float* __restrict__ Wx2, const float* __restrict__ bx2,
    const float* __restrict__ Wxf, const float* __restrict__ bxf,
    const float* __restrict__ Wxr, const float* __restrict__ bxr) {
    extern __shared__ float sm[];
    float* sWx  = sm;
    float* sWx1 = sWx  + 4096;
    float* sWx2 = sWx1 + 4096;
    float* sWxf = sWx2 + 4096;
    float* sWxr = sWxf + 4096;
    float* sIn  = sWxr + 4096;   // [64][128], reused for x / xp / xf / xr

    const int tid = threadIdx.x;
    const int b   = blockIdx.x >> 7;
    const int h   = blockIdx.x & 127;
    const size_t bh = (size_t)b * 128 + h;
    const size_t gbase = (size_t)b * C * HW + (size_t)h * W;

    for (int i = tid; i < 4096; i += 256) {
        int o = i >> 6, c = i & 63;
        int s = WIDX(o, c);
        sWx [s] = Wx [i];
        sWx1[s] = Wx1[i];
        sWx2[s] = Wx2[i];
        sWxf[s] = Wxf[i];
        sWxr[s] = Wxr[i];
    }
    for (int i = tid; i < 8192; i += 256) {
        int c = i >> 7, p = i & 127;
        sIn[i] = x[gbase + (size_t)c * HW + p];
    }
    __syncthreads();

    const int og = tid >> 4;
    const int wg = tid & 15;
    const int o0 = og * 4;
    float acc[4][8];

    // xp -> smem tile (aliased) + transposed split fp16 global
    proj_gemm(sWx, sIn, acc, o0, wg);
    __syncthreads();                 // everyone done reading x
#pragma unroll
    for (int j = 0; j < 4; j++) {
        float bb = __ldg(bx + o0 + j);
#pragma unroll
        for (int i = 0; i < 8; i++) acc[j][i] += bb;
    }
#pragma unroll
    for (int i = 0; i < 8; i++) {
        int p = wg + 16 * i;
        __half hi0, lo0, hi1, lo1, hi2, lo2, hi3, lo3;
        split16(acc[0][i], hi0, lo0);
        split16(acc[1][i], hi1, lo1);
        split16(acc[2][i], hi2, lo2);
        split16(acc[3][i], hi3, lo3);
#pragma unroll
        for (int j = 0; j < 4; j++) sIn[(o0 + j) * 128 + p] = acc[j][i];
        size_t wb = (bh * 128 + p) * 64 + o0;
        __half2 ph0 = __halves2half2(hi0, hi1), ph1 = __halves2half2(hi2, hi3);
        __half2 pl0 = __halves2half2(lo0, lo1), pl1 = __halves2half2(lo2, lo3);
        *(__half2*)(g_xpth + wb)     = ph0;
        *(__half2*)(g_xpth + wb + 2) = ph1;
        *(__half2*)(g_xptl + wb)     = pl0;
        *(__half2*)(g_xptl + wb + 2) = pl1;
    }
    __syncthreads();

    proj_gemm(sWx1, sIn, acc, o0, wg);
    store_cw(acc, bx1, g_x1h, g_x1l, bh, o0, wg);
    proj_gemm(sWx2, sIn, acc, o0, wg);
    __syncthreads();                 // done reading xp tile
    store_cw(acc, bx2, g_x2h, g_x2l, bh, o0, wg);

    for (int i = tid; i < 8192; i += 256) {
        int c = i >> 7, p = i & 127;
        sIn[i] = xf[gbase + (size_t)c * HW + p];
    }
    __syncthreads();
    proj_gemm(sWxf, sIn, acc, o0, wg);
    __syncthreads();
    store_cw(acc, bxf, g_xfh, g_xfl, bh, o0, wg);

    for (int i = tid; i < 8192; i += 256) {
        int c = i >> 7, p = i & 127;
        sIn[i] = xr[gbase + (size_t)c * HW + p];
    }
    __syncthreads();
    proj_gemm(sWxr, sIn, acc, o0, wg);
    store_cw(acc, bxr, g_xrh, g_xrl, bh, o0, wg);
}

// ---------------------------------------------------------------------------
// Kernel 2: tensor-core attention + conv-input packing.
// feat/x packed channel-last into g_inh (HI only — conv uses 2-term split).
// ---------------------------------------------------------------------------

#define AS1 136
#define ASP 72
#define ASS 72
#define ASF 129
#define O_X1H 0
#define O_X1L 8704
#define O_XFH 17408
#define O_XFL 26112
#define O_PH  34816
#define O_PL  44032
#define ATTN_SMEM_HALFS 53248   // 106496 bytes

__global__ __launch_bounds__(256, 2) void attn_mma_kernel(const float* __restrict__ x) {
    extern __shared__ __align__(16) __half smh[];
    __half* sX1h = smh + O_X1H;
    __half* sX1l = smh + O_X1L;
    __half* sXfh = smh + O_XFH;
    __half* sXfl = smh + O_XFL;
    __half* sPh  = smh + O_PH;
    __half* sPl  = smh + O_PL;
    __half* sSh  = smh + O_XFH;            // alias over sXf after GEMM1
    __half* sSl  = smh + O_XFH + 4608;
    float*  sF   = (float*)smh;            // alias over sX1 (8256 floats)

    const int tid = threadIdx.x;
    const int h = blockIdx.x, b = blockIdx.y;
    const size_t bh = (size_t)b * 128 + h;

    const int lane = tid & 31;
    const int wid = tid >> 5;
    const int lr = lane >> 2;
    const int lc2 = (lane & 3) * 2;
    const int grp = lane >> 3;
    const int gr  = lane & 7;

    uint32_t* outh = (uint32_t*)g_inh;
    const size_t wbase = bh * 128 * 96;

    // ---- load xpt ----
    {
        const __half* srcH = g_xpth + bh * 128 * 64;
        const __half* srcL = g_xptl + bh * 128 * 64;
        for (int idx = tid; idx < 1024; idx += 256) {
            int r = idx >> 3, g = idx & 7;
            *(uint4*)(sPh + r * ASP + g * 8) = *(const uint4*)(srcH + r * 64 + g * 8);
            *(uint4*)(sPl + r * ASP + g * 8) = *(const uint4*)(srcL + r * 64 + g * 8);
        }
    }
    // ---- pack x (channels 128..191), hi only ----
    {
        const size_t xbase = (size_t)b * C * HW + (size_t)h * W;
        for (int idx = tid; idx < 8192; idx += 256) {
            int c = idx >> 7, w = idx & 127;
            sF[c * ASF + w] = x[xbase + (size_t)c * HW + w];
        }
        __syncthreads();
        for (int idx = tid; idx < 4096; idx += 256) {
            int q = idx & 31, w = idx >> 5;
            int c = q * 2;
            __half2 ph = __halves2half2(__float2half_rn(sF[c * ASF + w]),
                                        __float2half_rn(sF[(c + 1) * ASF + w]));
            outh[wbase + (size_t)w * 96 + 64 + q] = *(uint32_t*)&ph;
        }
    }

    const int aoff1 = ((grp & 1) * 8 + gr) * AS1 + (grp >> 1) * 8;
    const int boff1 = ((grp >> 1) * 8 + gr) * AS1 + (grp & 1) * 8;
    const int aoffS = ((grp & 1) * 8 + gr) * ASS + (grp >> 1) * 8;
    const int boffP = ((grp >> 1) * 8 + gr) * ASP + (grp & 1) * 8;

    for (int pass = 0; pass < 2; pass++) {
        const __half* gAh = pass ? g_x2h : g_x1h;
        const __half* gAl = pass ? g_x2l : g_x1l;
        const __half* gBh = pass ? g_xrh : g_xfh;
        const __half* gBl = pass ? g_xrl : g_xfl;

        __syncthreads();
        {
            const size_t sb = bh * 64 * 128;
            for (int idx = tid; idx < 1024; idx += 256) {
                int r = idx >> 4, g = idx & 15;
                *(uint4*)(sX1h + r * AS1 + g * 8) = *(const uint4*)(gAh + sb + r * 128 + g * 8);
                *(uint4*)(sX1l + r * AS1 + g * 8) = *(const uint4*)(gAl + sb + r * 128 + g * 8);
                *(uint4*)(sXfh + r * AS1 + g * 8) = *(const uint4*)(gBh + sb + r * 128 + g * 8);
                *(uint4*)(sXfl + r * AS1 + g * 8) = *(const uint4*)(gBl + sb + r * 128 + g * 8);
            }
        }
        __syncthreads();

        // ---- GEMM1: score = x1 @ xfp^T ----
        float sacc[4][4];
#pragma unroll
        for (int nf = 0; nf < 4; nf++)
#pragma unroll
            for (int i = 0; i < 4; i++) sacc[nf][i] = 0.f;
        {
            const int m0 = (wid & 3) * 16, n0 = (wid >> 2) * 32;
#pragma unroll
            for (int ks = 0; ks < 8; ks++) {
                const int k0 = ks * 16;
                uint32_t bhf[4][2], blf[4][2];
#pragma unroll
                for (int ntp = 0; ntp < 2; ntp++) {
                    const int nb = (n0 + ntp * 16) * AS1 + k0 + boff1;
                    ldsm4(bhf[ntp * 2][0], bhf[ntp * 2][1], bhf[ntp * 2 + 1][0],
                          bhf[ntp * 2 + 1][1], sXfh + nb);
                    ldsm4(blf[ntp * 2][0], blf[ntp * 2][1], blf[ntp * 2 + 1][0],
                          blf[ntp * 2 + 1][1], sXfl + nb);
                }
                const int mb = m0 * AS1 + k0 + aoff1;
                uint32_t ah0, ah1, ah2, ah3, al0, al1, al2, al3;
                ldsm4(ah0, ah1, ah2, ah3, sX1h + mb);
                ldsm4(al0, al1, al2, al3, sX1l + mb);
#pragma unroll
                for (int nf = 0; nf < 4; nf++)
                    mma16816(sacc[nf], ah0, ah1, ah2, ah3, bhf[nf][0], bhf[nf][1]);
#pragma unroll
                for (int nf = 0; nf < 4; nf++)
                    mma16816(sacc[nf], al0, al1, al2, al3, bhf[nf][0], bhf[nf][1]);
#pragma unroll
                for (int nf = 0; nf < 4; nf++)
                    mma16816(sacc[nf], ah0, ah1, ah2, ah3, blf[nf][0], blf[nf][1]);
            }
        }
        __syncthreads();

        // ---- score -> smem split fp16 ----
        {
            const int m0 = (wid & 3) * 16, n0 = (wid >> 2) * 32;
#pragma unroll
            for (int nf = 0; nf < 4; nf++)
#pragma unroll
                for (int i = 0; i < 4; i++) {
                    int row = m0 + lr + (i >= 2 ? 8 : 0);
                    int col = n0 + nf * 8 + lc2 + (i & 1);
                    __half hi, lo;
                    split16(sacc[nf][i], hi, lo);
                    sSh[row * ASS + col] = hi;
                    sSl[row * ASS + col] = lo;
                }
        }
        __syncthreads();

        // ---- GEMM2: feat = score @ xp ----
        float facc[2][4][4];
#pragma unroll
        for (int mt = 0; mt < 2; mt++)
#pragma unroll
            for (int nf = 0; nf < 4; nf++)
#pragma unroll
                for (int i = 0; i < 4; i++) facc[mt][nf][i] = 0.f;
        {
            const int m0 = (wid & 1) * 32, n0 = (wid >> 1) * 32;
#pragma unroll
            for (int ks = 0; ks < 4; ks++) {
                const int k0 = ks * 16;
                uint32_t bhf[4][2], blf[4][2];
#pragma unroll
                for (int ntp = 0; ntp < 2; ntp++) {
                    const int nb = (n0 + ntp * 16) * ASP + k0 + boffP;
                    ldsm4(bhf[ntp * 2][0], bhf[ntp * 2][1], bhf[ntp * 2 + 1][0],
                          bhf[ntp * 2 + 1][1], sPh + nb);
                    ldsm4(blf[ntp * 2][0], blf[ntp * 2][1], blf[ntp * 2 + 1][0],
                          blf[ntp * 2 + 1][1], sPl + nb);
                }
#pragma unroll
                for (int mt = 0; mt < 2; mt++) {
                    const int mb = (m0 + mt * 16) * ASS + k0 + aoffS;
                    uint32_t ah0, ah1, ah2, ah3, al0, al1, al2, al3;
                    ldsm4(ah0, ah1, ah2, ah3, sSh + mb);
                    ldsm4(al0, al1, al2, al3, sSl + mb);
#pragma unroll
                    for (int nf = 0; nf < 4; nf++)
                        mma16816(facc[mt][nf], ah0, ah1, ah2, ah3, bhf[nf][0], bhf[nf][1]);
#pragma unroll
                    for (int nf = 0; nf < 4; nf++)
                        mma16816(facc[mt][nf], al0, al1, al2, al3, bhf[nf][0], bhf[nf][1]);
#pragma unroll
                    for (int nf = 0; nf < 4; nf++)
                        mma16816(facc[mt][nf], ah0, ah1, ah2, ah3, blf[nf][0], blf[nf][1]);
                }
            }
        }
        {
            const int m0 = (wid & 1) * 32, n0 = (wid >> 1) * 32;
#pragma unroll
            for (int mt = 0; mt < 2; mt++)
#pragma unroll
                for (int nf = 0; nf < 4; nf++)
#pragma unroll
                    for (int i = 0; i < 4; i++) {
                        int row = m0 + mt * 16 + lr + (i >= 2 ? 8 : 0);
                        int col = n0 + nf * 8 + lc2 + (i & 1);
                        sF[row * ASF + col] = facc[mt][nf][i];
                    }
        }
        __syncthreads();

        // ---- pack feat (channels pass*64 ..), hi only ----
        for (int idx = tid; idx < 4096; idx += 256) {
            int q = idx & 31, w = idx >> 5;
            int c = q * 2;
            __half2 ph = __halves2half2(__float2half_rn(sF[c * ASF + w]),
                                        __float2half_rn(sF[(c + 1) * ASF + w]));
            outh[wbase + (size_t)w * 96 + pass * 32 + q] = *(uint32_t*)&ph;
        }
    }
}

// ---------------------------------------------------------------------------
// Kernel 3a: weight prep (hi + lo).
// ---------------------------------------------------------------------------
__global__ void wprep_kernel(const float* __restrict__ Wm) {
    const int kc = blockIdx.x;       // 0..53
    const int o  = threadIdx.x;      // 0..191
    const int tap = kc / 6;
    const int ch0 = (kc - tap * 6) * 32;
#pragma unroll
    for (int j = 0; j < 32; j++) {
        float v  = Wm[((size_t)o * 192 + ch0 + j) * 9 + tap];
        __half hi, lo;
        split16(v, hi, lo);
        size_t d = ((size_t)kc * 192 + o) * 32 + j;
        g_wh16[d] = hi;
        g_wl16[d] = lo;
    }
}

// ---------------------------------------------------------------------------
// Kernel 3b: 2-term fp16 split conv (W_hi·In + W_lo·In) + BN + ReLU.
// ---------------------------------------------------------------------------

#define AST 40
#define A_TILE (192 * AST)
#define B_TILE (128 * AST)
#define CONV_SMEM_BYTES ((4 * A_TILE + 2 * B_TILE) * 2 + 384 * 4)

__global__ __launch_bounds__(256, 2) void conv_mma_kernel(
    const float* __restrict__ bm, const float* __restrict__ gamma,
    const float* __restrict__ beta, const float* __restrict__ mean,
    const float* __restrict__ var, float* __restrict__ out) {
    extern __shared__ __align__(16) __half smh[];
    __half* sAh = smh;                        // [2][A_TILE]
    __half* sAl = sAh + 2 * A_TILE;           // [2][A_TILE]
    __half* sBh = sAl + 2 * A_TILE;           // [2][B_TILE]
    float* ssc = (float*)(sBh + 2 * B_TILE);
    float* sbi = ssc + 192;

    const int tid = threadIdx.x;
    const int h = blockIdx.x, b = blockIdx.y;

    if (tid < 192) {
        float scv = gamma[tid] * rsqrtf(var[tid] + 1e-4f);
        ssc[tid] = scv;
        sbi[tid] = (bm[tid] - mean[tid]) * scv + beta[tid];
    }

    const int lane = tid & 31;
    const int wid = tid >> 5;
    const int wm = wid & 1;
    const int wn = wid >> 1;
    const int lr = lane >> 2;
    const int lc2 = (lane & 3) * 2;
    const int grp = lane >> 3;
    const int gr  = lane & 7;
    const int aoff = ((grp & 1) * 8 + gr) * AST + (grp >> 1) * 8;
    const int boff = ((grp >> 1) * 8 + gr) * AST + (grp & 1) * 8;

    float acc[6][4][4];
#pragma unroll
    for (int mt = 0; mt < 6; mt++)
#pragma unroll
        for (int nt = 0; nt < 4; nt++)
#pragma unroll
            for (int i = 0; i < 4; i++) acc[mt][nt][i] = 0.f;

    auto stage = [&](int kc, int buf) {
        const int tap = kc / 6;
        const int ch0 = (kc - tap * 6) * 32;
        const int dh = tap / 3 - 1;
        const int dw = tap - (tap / 3) * 3 - 1;
        const int row = h + dh;
        const bool rok = ((unsigned)row < 128u);
        const __half* wh = g_wh16 + (size_t)kc * 6144;
        const __half* wl = g_wl16 + (size_t)kc * 6144;
#pragma unroll
        for (int i = 0; i < 3; i++) {
            int idx = tid + i * 256;
            int r = idx >> 2, g = idx & 3;
            cpa16(sAh + buf * A_TILE + r * AST + g * 8, wh + r * 32 + g * 8);
            cpa16(sAl + buf * A_TILE + r * AST + g * 8, wl + r * 32 + g * 8);
        }
        const size_t rowbase = ((size_t)(b * 128 + row) * 128) * 192;
#pragma unroll
        for (int i = 0; i < 2; i++) {
            int idx = tid + i * 256;
            int r = idx >> 2, g = idx & 3;
            int wsrc = r + dw;
            bool ok = rok && ((unsigned)wsrc < 128u);
            __half* dh_ = sBh + buf * B_TILE + r * AST + g * 8;
            if (ok) {
                cpa16(dh_, g_inh + rowbase + (size_t)wsrc * 192 + ch0 + g * 8);
            } else {
                *(uint4*)dh_ = make_uint4(0, 0, 0, 0);
            }
        }
    };

    stage(0, 0);
    CP_COMMIT();

    for (int kc = 0; kc < 54; kc++) {
        const int buf = kc & 1;
        if (kc < 53) stage(kc + 1, (kc + 1) & 1);
        CP_COMMIT();
        CP_WAIT1();
        __syncthreads();

        const __half* bAh = sAh + buf * A_TILE;
        const __half* bAl = sAl + buf * A_TILE;
        const __half* bBh = sBh + buf * B_TILE;

#pragma unroll
        for (int ks = 0; ks < 2; ks++) {
            const int kk = ks * 16;
            uint32_t bh[4][2];
#pragma unroll
            for (int ntp = 0; ntp < 2; ntp++) {
                const int nb = (wn * 32 + ntp * 16) * AST + kk + boff;
                ldsm4(bh[ntp * 2][0], bh[ntp * 2][1], bh[ntp * 2 + 1][0],
                      bh[ntp * 2 + 1][1], bBh + nb);
            }
#pragma unroll
            for (int mt = 0; mt < 6; mt++) {
                const int mb = (wm * 96 + mt * 16) * AST + kk + aoff;
                uint32_t ah0, ah1, ah2, ah3, al0, al1, al2, al3;
                ldsm4(ah0, ah1, ah2, ah3, bAh + mb);
                ldsm4(al0, al1, al2, al3, bAl + mb);
#pragma unroll
                for (int nt = 0; nt < 4; nt++)
                    mma16816(acc[mt][nt], ah0, ah1, ah2, ah3, bh[nt][0], bh[nt][1]);
#pragma unroll
                for (int nt = 0; nt < 4; nt++)
                    mma16816(acc[mt][nt], al0, al1, al2, al3, bh[nt][0], bh[nt][1]);
            }
        }
        __syncthreads();
    }

#pragma unroll
    for (int mt = 0; mt < 6; mt++) {
        int o0 = wm * 96 + mt * 16 + lr;
        float s0 = ssc[o0],     bi0 = sbi[o0];
        float s1 = ssc[o0 + 8], bi1 = sbi[o0 + 8];
#pragma unroll
        for (int nt = 0; nt < 4; nt++) {
            int wcol = wn * 32 + nt * 8 + lc2;
            float2 v0, v1;
            v0.x = fmaxf(acc[mt][nt][0] * s0 + bi0, 0.f);
            v0.y = fmaxf(acc[mt][nt][1] * s0 + bi0, 0.f);
            v1.x = fmaxf(acc[mt][nt][2] * s1 + bi1, 0.f);
            v1.y = fmaxf(acc[mt][nt][3] * s1 + bi1, 0.f);
            size_t p0 = (((size_t)b * C3 + o0)     * H + h) * W + wcol;
            size_t p1 = (((size_t)b * C3 + o0 + 8) * H + h) * W + wcol;
            *(float2*)(out + p0) = v0;
            *(float2*)(out + p1) = v1;
        }
    }
}

// ---------------------------------------------------------------------------

extern "C" void kernel_launch(void* const* d_in, const int* in_sizes, int n_in,
                              void* d_out, int out_size) {
    const float* x    = (const float*)d_in[0];
    const float* xf   = (const float*)d_in[1];
    const float* xr   = (const float*)d_in[2];
    const float* Wx   = (const float*)d_in[3];
    const float* bx   = (const float*)d_in[4];
    const float* Wx1  = (const float*)d_in[5];
    const float* bx1  = (const float*)d_in[6];
    const float* Wx2  = (const float*)d_in[7];
    const float* bx2  = (const float*)d_in[8];
    const float* Wxf  = (const float*)d_in[9];
    const float* bxf  = (const float*)d_in[10];
    const float* Wxr  = (const float*)d_in[11];
    const float* bxr  = (const float*)d_in[12];
    const float* Wm   = (const float*)d_in[13];
    const float* bm   = (const float*)d_in[14];
    const float* gam  = (const float*)d_in[15];
    const float* bet  = (const float*)d_in[16];
    const float* mean = (const float*)d_in[17];
    const float* var  = (const float*)d_in[18];
    float* out = (float*)d_out;

    const int proj_smem = PROJ_SMEM_FLOATS * 4;
    const int attn_smem = ATTN_SMEM_HALFS * 2;
    const int conv_smem = CONV_SMEM_BYTES;
    cudaFuncSetAttribute(proj_kernel, cudaFuncAttributeMaxDynamicSharedMemorySize, proj_smem);
    cudaFuncSetAttribute(attn_mma_kernel, cudaFuncAttributeMaxDynamicSharedMemorySize, attn_smem);
    cudaFuncSetAttribute(conv_mma_kernel, cudaFuncAttributeMaxDynamicSharedMemorySize, conv_smem);

    proj_kernel<<<B * H, 256, proj_smem>>>(x, xf, xr, Wx, bx, Wx1, bx1,
                                           Wx2, bx2, Wxf, bxf, Wxr, bxr);
    wprep_kernel<<<54, 192>>>(Wm);
    attn_mma_kernel<<<dim3(H, B), 256, attn_smem>>>(x);
    conv_mma_kernel<<<dim3(H, B), 256, conv_smem>>>(bm, gam, bet, mean, var, out);
}

// round 11
// speedup vs baseline: 5.8408x; 1.2981x over previous
#include <cuda_runtime.h>
#include <cuda_fp16.h>
#include <cstdint>

// Problem constants
constexpr int C   = 64;
constexpr int H   = 128;
constexpr int W   = 128;
constexpr int HW  = H * W;          // 16384
constexpr int B   = 8;
constexpr int C3  = 192;

// ---------------------------------------------------------------------------
// Scratch (device globals). Attention intermediates split fp16 (hi + lo);
// conv operands are plain fp16 (1-term, validated error model).
// ---------------------------------------------------------------------------
__device__ __half g_x1h[(size_t)B * H * C * W], g_x1l[(size_t)B * H * C * W];
__device__ __half g_x2h[(size_t)B * H * C * W], g_x2l[(size_t)B * H * C * W];
__device__ __half g_xfh[(size_t)B * H * C * W], g_xfl[(size_t)B * H * C * W];
__device__ __half g_xrh[(size_t)B * H * C * W], g_xrl[(size_t)B * H * C * W];
__device__ __half g_xpth[(size_t)B * H * W * C], g_xptl[(size_t)B * H * W * C];
// conv input, channel-last [b][h][w][192] — fp16
__device__ __half g_inh[(size_t)B * H * W * C3];
// conv weights, chunked [kc][o][32] — fp16
__device__ __half g_wh16[54 * 192 * 32];

// ---------------------------------------------------------------------------
// Helpers
// ---------------------------------------------------------------------------
__device__ __forceinline__ void cpa16(void* dst, const void* src) {
    uint32_t d = (uint32_t)__cvta_generic_to_shared(dst);
    asm volatile("cp.async.cg.shared.global [%0], [%1], 16;" :: "r"(d), "l"(src));
}
#define CP_COMMIT() asm volatile("cp.async.commit_group;" ::: "memory")
#define CP_WAIT1()  asm volatile("cp.async.wait_group 1;" ::: "memory")

__device__ __forceinline__ void mma16816(float acc[4], uint32_t a0, uint32_t a1,
                                         uint32_t a2, uint32_t a3,
                                         uint32_t b0, uint32_t b1) {
    asm volatile(
        "mma.sync.aligned.m16n8k16.row.col.f32.f16.f16.f32 "
        "{%0,%1,%2,%3}, {%4,%5,%6,%7}, {%8,%9}, {%0,%1,%2,%3};"
        : "+f"(acc[0]), "+f"(acc[1]), "+f"(acc[2]), "+f"(acc[3])
        : "r"(a0), "r"(a1), "r"(a2), "r"(a3), "r"(b0), "r"(b1));
}

__device__ __forceinline__ void ldsm4(uint32_t& r0, uint32_t& r1, uint32_t& r2,
                                      uint32_t& r3, const __half* p) {
    uint32_t a = (uint32_t)__cvta_generic_to_shared(p);
    asm volatile("ldmatrix.sync.aligned.m8n8.x4.shared.b16 {%0,%1,%2,%3}, [%4];"
                 : "=r"(r0), "=r"(r1), "=r"(r2), "=r"(r3) : "r"(a));
}

__device__ __forceinline__ void split16(float v, __half& hi, __half& lo) {
    hi = __float2half_rn(v);
    lo = __float2half_rn(v - __half2float(hi));
}

// ---------------------------------------------------------------------------
// Kernel 1: pointwise projections (fp32 register GEMM), outputs split fp16.
// ---------------------------------------------------------------------------

#define WIDX(o, c) (((c) << 6) | ((o) ^ ((c) & 31)))
#define PROJ_SMEM_FLOATS (5 * 4096 + 64 * 128)

__device__ __forceinline__ void proj_gemm(const float* __restrict__ sW,
                                          const float* __restrict__ sIn,
                                          float acc[4][8], int o0, int wg) {
#pragma unroll
    for (int j = 0; j < 4; j++)
#pragma unroll
        for (int i = 0; i < 8; i++) acc[j][i] = 0.f;
    for (int c = 0; c < 64; c++) {
        float in[8];
#pragma unroll
        for (int i = 0; i < 8; i++) in[i] = sIn[c * 128 + wg + 16 * i];
        float wv[4];
#pragma unroll
        for (int j = 0; j < 4; j++) wv[j] = sW[WIDX(o0 + j, c)];
#pragma unroll
        for (int j = 0; j < 4; j++)
#pragma unroll
            for (int i = 0; i < 8; i++) acc[j][i] += wv[j] * in[i];
    }
}

__device__ __forceinline__ void store_cw(float acc[4][8], const float* bias,
                                         __half* dh, __half* dl,
                                         size_t bh, int o0, int wg) {
#pragma unroll
    for (int j = 0; j < 4; j++) {
        float bb = __ldg(bias + o0 + j);
        size_t rb = (bh * 64 + o0 + j) * 128;
#pragma unroll
        for (int i = 0; i < 8; i++) {
            __half hi, lo;
            split16(acc[j][i] + bb, hi, lo);
            dh[rb + wg + 16 * i] = hi;
            dl[rb + wg + 16 * i] = lo;
        }
    }
}

__global__ __launch_bounds__(256, 2) void proj_kernel(
    const float* __restrict__ x, const float* __restrict__ xf, const float* __restrict__ xr,
    const float* __restrict__ Wx,  const float* __restrict__ bx,
    const float* __restrict__ Wx1, const float* __restrict__ bx1,
    const float* __restrict__ Wx2, const float* __restrict__ bx2,
    const float* __restrict__ Wxf, const float* __restrict__ bxf,
    const float* __restrict__ Wxr, const float* __restrict__ bxr) {
    extern __shared__ float sm[];
    float* sWx  = sm;
    float* sWx1 = sWx  + 4096;
    float* sWx2 = sWx1 + 4096;
    float* sWxf = sWx2 + 4096;
    float* sWxr = sWxf + 4096;
    float* sIn  = sWxr + 4096;   // [64][128], reused for x / xp / xf / xr

    const int tid = threadIdx.x;
    const int b   = blockIdx.x >> 7;
    const int h   = blockIdx.x & 127;
    const size_t bh = (size_t)b * 128 + h;
    const size_t gbase = (size_t)b * C * HW + (size_t)h * W;

    for (int i = tid; i < 4096; i += 256) {
        int o = i >> 6, c = i & 63;
        int s = WIDX(o, c);
        sWx [s] = Wx [i];
        sWx1[s] = Wx1[i];
        sWx2[s] = Wx2[i];
        sWxf[s] = Wxf[i];
        sWxr[s] = Wxr[i];
    }
    for (int i = tid; i < 8192; i += 256) {
        int c = i >> 7, p = i & 127;
        sIn[i] = x[gbase + (size_t)c * HW + p];
    }
    __syncthreads();

    const int og = tid >> 4;
    const int wg = tid & 15;
    const int o0 = og * 4;
    float acc[4][8];

    // xp -> smem tile (aliased) + transposed split fp16 global
    proj_gemm(sWx, sIn, acc, o0, wg);
    __syncthreads();                 // everyone done reading x
#pragma unroll
    for (int j = 0; j < 4; j++) {
        float bb = __ldg(bx + o0 + j);
#pragma unroll
        for (int i = 0; i < 8; i++) acc[j][i] += bb;
    }
#pragma unroll
    for (int i = 0; i < 8; i++) {
        int p = wg + 16 * i;
        __half hi0, lo0, hi1, lo1, hi2, lo2, hi3, lo3;
        split16(acc[0][i], hi0, lo0);
        split16(acc[1][i], hi1, lo1);
        split16(acc[2][i], hi2, lo2);
        split16(acc[3][i], hi3, lo3);
#pragma unroll
        for (int j = 0; j < 4; j++) sIn[(o0 + j) * 128 + p] = acc[j][i];
        size_t wb = (bh * 128 + p) * 64 + o0;
        __half2 ph0 = __halves2half2(hi0, hi1), ph1 = __halves2half2(hi2, hi3);
        __half2 pl0 = __halves2half2(lo0, lo1), pl1 = __halves2half2(lo2, lo3);
        *(__half2*)(g_xpth + wb)     = ph0;
        *(__half2*)(g_xpth + wb + 2) = ph1;
        *(__half2*)(g_xptl + wb)     = pl0;
        *(__half2*)(g_xptl + wb + 2) = pl1;
    }
    __syncthreads();

    proj_gemm(sWx1, sIn, acc, o0, wg);
    store_cw(acc, bx1, g_x1h, g_x1l, bh, o0, wg);
    proj_gemm(sWx2, sIn, acc, o0, wg);
    __syncthreads();                 // done reading xp tile
    store_cw(acc, bx2, g_x2h, g_x2l, bh, o0, wg);

    for (int i = tid; i < 8192; i += 256) {
        int c = i >> 7, p = i & 127;
        sIn[i] = xf[gbase + (size_t)c * HW + p];
    }
    __syncthreads();
    proj_gemm(sWxf, sIn, acc, o0, wg);
    __syncthreads();
    store_cw(acc, bxf, g_xfh, g_xfl, bh, o0, wg);

    for (int i = tid; i < 8192; i += 256) {
        int c = i >> 7, p = i & 127;
        sIn[i] = xr[gbase + (size_t)c * HW + p];
    }
    __syncthreads();
    proj_gemm(sWxr, sIn, acc, o0, wg);
    store_cw(acc, bxr, g_xrh, g_xrl, bh, o0, wg);
}

// ---------------------------------------------------------------------------
// Kernel 2: tensor-core attention + conv-input packing.
// Attention keeps full 3-term split; conv input packed as plain fp16.
// ---------------------------------------------------------------------------

#define AS1 136
#define ASP 72
#define ASS 72
#define ASF 129
#define O_X1H 0
#define O_X1L 8704
#define O_XFH 17408
#define O_XFL 26112
#define O_PH  34816
#define O_PL  44032
#define ATTN_SMEM_HALFS 53248   // 106496 bytes

__global__ __launch_bounds__(256, 2) void attn_mma_kernel(const float* __restrict__ x) {
    extern __shared__ __align__(16) __half smh[];
    __half* sX1h = smh + O_X1H;
    __half* sX1l = smh + O_X1L;
    __half* sXfh = smh + O_XFH;
    __half* sXfl = smh + O_XFL;
    __half* sPh  = smh + O_PH;
    __half* sPl  = smh + O_PL;
    __half* sSh  = smh + O_XFH;            // alias over sXf after GEMM1
    __half* sSl  = smh + O_XFH + 4608;
    float*  sF   = (float*)smh;            // alias over sX1 (8256 floats)

    const int tid = threadIdx.x;
    const int h = blockIdx.x, b = blockIdx.y;
    const size_t bh = (size_t)b * 128 + h;

    const int lane = tid & 31;
    const int wid = tid >> 5;
    const int lr = lane >> 2;
    const int lc2 = (lane & 3) * 2;
    const int grp = lane >> 3;
    const int gr  = lane & 7;

    uint32_t* outh = (uint32_t*)g_inh;
    const size_t wbase = bh * 128 * 96;

    // ---- load xpt ----
    {
        const __half* srcH = g_xpth + bh * 128 * 64;
        const __half* srcL = g_xptl + bh * 128 * 64;
        for (int idx = tid; idx < 1024; idx += 256) {
            int r = idx >> 3, g = idx & 7;
            *(uint4*)(sPh + r * ASP + g * 8) = *(const uint4*)(srcH + r * 64 + g * 8);
            *(uint4*)(sPl + r * ASP + g * 8) = *(const uint4*)(srcL + r * 64 + g * 8);
        }
    }
    // ---- pack x (channels 128..191) ----
    {
        const size_t xbase = (size_t)b * C * HW + (size_t)h * W;
        for (int idx = tid; idx < 8192; idx += 256) {
            int c = idx >> 7, w = idx & 127;
            sF[c * ASF + w] = x[xbase + (size_t)c * HW + w];
        }
        __syncthreads();
        for (int idx = tid; idx < 4096; idx += 256) {
            int q = idx & 31, w = idx >> 5;
            int c = q * 2;
            __half2 ph = __halves2half2(__float2half_rn(sF[c * ASF + w]),
                                        __float2half_rn(sF[(c + 1) * ASF + w]));
            outh[wbase + (size_t)w * 96 + 64 + q] = *(uint32_t*)&ph;
        }
    }

    const int aoff1 = ((grp & 1) * 8 + gr) * AS1 + (grp >> 1) * 8;
    const int boff1 = ((grp >> 1) * 8 + gr) * AS1 + (grp & 1) * 8;
    const int aoffS = ((grp & 1) * 8 + gr) * ASS + (grp >> 1) * 8;
    const int boffP = ((grp >> 1) * 8 + gr) * ASP + (grp & 1) * 8;

    for (int pass = 0; pass < 2; pass++) {
        const __half* gAh = pass ? g_x2h : g_x1h;
        const __half* gAl = pass ? g_x2l : g_x1l;
        const __half* gBh = pass ? g_xrh : g_xfh;
        const __half* gBl = pass ? g_xrl : g_xfl;

        __syncthreads();
        {
            const size_t sb = bh * 64 * 128;
            for (int idx = tid; idx < 1024; idx += 256) {
                int r = idx >> 4, g = idx & 15;
                *(uint4*)(sX1h + r * AS1 + g * 8) = *(const uint4*)(gAh + sb + r * 128 + g * 8);
                *(uint4*)(sX1l + r * AS1 + g * 8) = *(const uint4*)(gAl + sb + r * 128 + g * 8);
                *(uint4*)(sXfh + r * AS1 + g * 8) = *(const uint4*)(gBh + sb + r * 128 + g * 8);
                *(uint4*)(sXfl + r * AS1 + g * 8) = *(const uint4*)(gBl + sb + r * 128 + g * 8);
            }
        }
        __syncthreads();

        // ---- GEMM1: score = x1 @ xfp^T ----
        float sacc[4][4];
#pragma unroll
        for (int nf = 0; nf < 4; nf++)
#pragma unroll
            for (int i = 0; i < 4; i++) sacc[nf][i] = 0.f;
        {
            const int m0 = (wid & 3) * 16, n0 = (wid >> 2) * 32;
#pragma unroll
            for (int ks = 0; ks < 8; ks++) {
                const int k0 = ks * 16;
                uint32_t bhf[4][2], blf[4][2];
#pragma unroll
                for (int ntp = 0; ntp < 2; ntp++) {
                    const int nb = (n0 + ntp * 16) * AS1 + k0 + boff1;
                    ldsm4(bhf[ntp * 2][0], bhf[ntp * 2][1], bhf[ntp * 2 + 1][0],
                          bhf[ntp * 2 + 1][1], sXfh + nb);
                    ldsm4(blf[ntp * 2][0], blf[ntp * 2][1], blf[ntp * 2 + 1][0],
                          blf[ntp * 2 + 1][1], sXfl + nb);
                }
                const int mb = m0 * AS1 + k0 + aoff1;
                uint32_t ah0, ah1, ah2, ah3, al0, al1, al2, al3;
                ldsm4(ah0, ah1, ah2, ah3, sX1h + mb);
                ldsm4(al0, al1, al2, al3, sX1l + mb);
#pragma unroll
                for (int nf = 0; nf < 4; nf++)
                    mma16816(sacc[nf], ah0, ah1, ah2, ah3, bhf[nf][0], bhf[nf][1]);
#pragma unroll
                for (int nf = 0; nf < 4; nf++)
                    mma16816(sacc[nf], al0, al1, al2, al3, bhf[nf][0], bhf[nf][1]);
#pragma unroll
                for (int nf = 0; nf < 4; nf++)
                    mma16816(sacc[nf], ah0, ah1, ah2, ah3, blf[nf][0], blf[nf][1]);
            }
        }
        __syncthreads();

        // ---- score -> smem split fp16 ----
        {
            const int m0 = (wid & 3) * 16, n0 = (wid >> 2) * 32;
#pragma unroll
            for (int nf = 0; nf < 4; nf++)
#pragma unroll
                for (int i = 0; i < 4; i++) {
                    int row = m0 + lr + (i >= 2 ? 8 : 0);
                    int col = n0 + nf * 8 + lc2 + (i & 1);
                    __half hi, lo;
                    split16(sacc[nf][i], hi, lo);
                    sSh[row * ASS + col] = hi;
                    sSl[row * ASS + col] = lo;
                }
        }
        __syncthreads();

        // ---- GEMM2: feat = score @ xp ----
        float facc[2][4][4];
#pragma unroll
        for (int mt = 0; mt < 2; mt++)
#pragma unroll
            for (int nf = 0; nf < 4; nf++)
#pragma unroll
                for (int i = 0; i < 4; i++) facc[mt][nf][i] = 0.f;
        {
            const int m0 = (wid & 1) * 32, n0 = (wid >> 1) * 32;
#pragma unroll
            for (int ks = 0; ks < 4; ks++) {
                const int k0 = ks * 16;
                uint32_t bhf[4][2], blf[4][2];
#pragma unroll
                for (int ntp = 0; ntp < 2; ntp++) {
                    const int nb = (n0 + ntp * 16) * ASP + k0 + boffP;
                    ldsm4(bhf[ntp * 2][0], bhf[ntp * 2][1], bhf[ntp * 2 + 1][0],
                          bhf[ntp * 2 + 1][1], sPh + nb);
                    ldsm4(blf[ntp * 2][0], blf[ntp * 2][1], blf[ntp * 2 + 1][0],
                          blf[ntp * 2 + 1][1], sPl + nb);
                }
#pragma unroll
                for (int mt = 0; mt < 2; mt++) {
                    const int mb = (m0 + mt * 16) * ASS + k0 + aoffS;
                    uint32_t ah0, ah1, ah2, ah3, al0, al1, al2, al3;
                    ldsm4(ah0, ah1, ah2, ah3, sSh + mb);
                    ldsm4(al0, al1, al2, al3, sSl + mb);
#pragma unroll
                    for (int nf = 0; nf < 4; nf++)
                        mma16816(facc[mt][nf], ah0, ah1, ah2, ah3, bhf[nf][0], bhf[nf][1]);
#pragma unroll
                    for (int nf = 0; nf < 4; nf++)
                        mma16816(facc[mt][nf], al0, al1, al2, al3, bhf[nf][0], bhf[nf][1]);
#pragma unroll
                    for (int nf = 0; nf < 4; nf++)
                        mma16816(facc[mt][nf], ah0, ah1, ah2, ah3, blf[nf][0], blf[nf][1]);
                }
            }
        }
        {
            const int m0 = (wid & 1) * 32, n0 = (wid >> 1) * 32;
#pragma unroll
            for (int mt = 0; mt < 2; mt++)
#pragma unroll
                for (int nf = 0; nf < 4; nf++)
#pragma unroll
                    for (int i = 0; i < 4; i++) {
                        int row = m0 + mt * 16 + lr + (i >= 2 ? 8 : 0);
                        int col = n0 + nf * 8 + lc2 + (i & 1);
                        sF[row * ASF + col] = facc[mt][nf][i];
                    }
        }
        __syncthreads();

        // ---- pack feat (channels pass*64 ..) ----
        for (int idx = tid; idx < 4096; idx += 256) {
            int q = idx & 31, w = idx >> 5;
            int c = q * 2;
            __half2 ph = __halves2half2(__float2half_rn(sF[c * ASF + w]),
                                        __float2half_rn(sF[(c + 1) * ASF + w]));
            outh[wbase + (size_t)w * 96 + pass * 32 + q] = *(uint32_t*)&ph;
        }
    }
}

// ---------------------------------------------------------------------------
// Kernel 3a: weight prep (fp16, hi only).
// ---------------------------------------------------------------------------
__global__ void wprep_kernel(const float* __restrict__ Wm) {
    const int kc = blockIdx.x;       // 0..53
    const int o  = threadIdx.x;      // 0..191
    const int tap = kc / 6;
    const int ch0 = (kc - tap * 6) * 32;
#pragma unroll
    for (int j = 0; j < 32; j++) {
        float v  = Wm[((size_t)o * 192 + ch0 + j) * 9 + tap];
        g_wh16[((size_t)kc * 192 + o) * 32 + j] = __float2half_rn(v);
    }
}

// ---------------------------------------------------------------------------
// Kernel 3b: pure fp16 mma.sync implicit-GEMM conv + BN + ReLU.
// ---------------------------------------------------------------------------

#define AST 40
#define A_TILE (192 * AST)
#define B_TILE (128 * AST)
#define CONV_SMEM_BYTES ((2 * A_TILE + 2 * B_TILE) * 2 + 384 * 4)

__global__ __launch_bounds__(256, 2) void conv_mma_kernel(
    const float* __restrict__ bm, const float* __restrict__ gamma,
    const float* __restrict__ beta, const float* __restrict__ mean,
    const float* __restrict__ var, float* __restrict__ out) {
    extern __shared__ __align__(16) __half smh[];
    __half* sAh = smh;                        // [2][A_TILE]
    __half* sBh = sAh + 2 * A_TILE;           // [2][B_TILE]
    float* ssc = (float*)(sBh + 2 * B_TILE);
    float* sbi = ssc + 192;

    const int tid = threadIdx.x;
    const int h = blockIdx.x, b = blockIdx.y;

    if (tid < 192) {
        float scv = gamma[tid] * rsqrtf(var[tid] + 1e-4f);
        ssc[tid] = scv;
        sbi[tid] = (bm[tid] - mean[tid]) * scv + beta[tid];
    }

    const int lane = tid & 31;
    const int wid = tid >> 5;
    const int wm = wid & 1;
    const int wn = wid >> 1;
    const int lr = lane >> 2;
    const int lc2 = (lane & 3) * 2;
    const int grp = lane >> 3;
    const int gr  = lane & 7;
    const int aoff = ((grp & 1) * 8 + gr) * AST + (grp >> 1) * 8;
    const int boff = ((grp >> 1) * 8 + gr) * AST + (grp & 1) * 8;

    float acc[6][4][4];
#pragma unroll
    for (int mt = 0; mt < 6; mt++)
#pragma unroll
        for (int nt = 0; nt < 4; nt++)
#pragma unroll
            for (int i = 0; i < 4; i++) acc[mt][nt][i] = 0.f;

    auto stage = [&](int kc, int buf) {
        const int tap = kc / 6;
        const int ch0 = (kc - tap * 6) * 32;
        const int dh = tap / 3 - 1;
        const int dw = tap - (tap / 3) * 3 - 1;
        const int row = h + dh;
        const bool rok = ((unsigned)row < 128u);
        const __half* wh = g_wh16 + (size_t)kc * 6144;
#pragma unroll
        for (int i = 0; i < 3; i++) {
            int idx = tid + i * 256;
            int r = idx >> 2, g = idx & 3;
            cpa16(sAh + buf * A_TILE + r * AST + g * 8, wh + r * 32 + g * 8);
        }
        const size_t rowbase = ((size_t)(b * 128 + row) * 128) * 192;
#pragma unroll
        for (int i = 0; i < 2; i++) {
            int idx = tid + i * 256;
            int r = idx >> 2, g = idx & 3;
            int wsrc = r + dw;
            bool ok = rok && ((unsigned)wsrc < 128u);
            __half* dh_ = sBh + buf * B_TILE + r * AST + g * 8;
            if (ok) {
                cpa16(dh_, g_inh + rowbase + (size_t)wsrc * 192 + ch0 + g * 8);
            } else {
                *(uint4*)dh_ = make_uint4(0, 0, 0, 0);
            }
        }
    };

    stage(0, 0);
    CP_COMMIT();

    for (int kc = 0; kc < 54; kc++) {
        const int buf = kc & 1;
        if (kc < 53) stage(kc + 1, (kc + 1) & 1);
        CP_COMMIT();
        CP_WAIT1();
        __syncthreads();

        const __half* bAh = sAh + buf * A_TILE;
        const __half* bBh = sBh + buf * B_TILE;

#pragma unroll
        for (int ks = 0; ks < 2; ks++) {
            const int kk = ks * 16;
            uint32_t bh[4][2];
#pragma unroll
            for (int ntp = 0; ntp < 2; ntp++) {
                const int nb = (wn * 32 + ntp * 16) * AST + kk + boff;
                ldsm4(bh[ntp * 2][0], bh[ntp * 2][1], bh[ntp * 2 + 1][0],
                      bh[ntp * 2 + 1][1], bBh + nb);
            }
#pragma unroll
            for (int mt = 0; mt < 6; mt++) {
                const int mb = (wm * 96 + mt * 16) * AST + kk + aoff;
                uint32_t ah0, ah1, ah2, ah3;
                ldsm4(ah0, ah1, ah2, ah3, bAh + mb);
#pragma unroll
                for (int nt = 0; nt < 4; nt++)
                    mma16816(acc[mt][nt], ah0, ah1, ah2, ah3, bh[nt][0], bh[nt][1]);
            }
        }
        __syncthreads();
    }

#pragma unroll
    for (int mt = 0; mt < 6; mt++) {
        int o0 = wm * 96 + mt * 16 + lr;
        float s0 = ssc[o0],     bi0 = sbi[o0];
        float s1 = ssc[o0 + 8], bi1 = sbi[o0 + 8];
#pragma unroll
        for (int nt = 0; nt < 4; nt++) {
            int wcol = wn * 32 + nt * 8 + lc2;
            float2 v0, v1;
            v0.x = fmaxf(acc[mt][nt][0] * s0 + bi0, 0.f);
            v0.y = fmaxf(acc[mt][nt][1] * s0 + bi0, 0.f);
            v1.x = fmaxf(acc[mt][nt][2] * s1 + bi1, 0.f);
            v1.y = fmaxf(acc[mt][nt][3] * s1 + bi1, 0.f);
            size_t p0 = (((size_t)b * C3 + o0)     * H + h) * W + wcol;
            size_t p1 = (((size_t)b * C3 + o0 + 8) * H + h) * W + wcol;
            *(float2*)(out + p0) = v0;
            *(float2*)(out + p1) = v1;
        }
    }
}

// ---------------------------------------------------------------------------

extern "C" void kernel_launch(void* const* d_in, const int* in_sizes, int n_in,
                              void* d_out, int out_size) {
    const float* x    = (const float*)d_in[0];
    const float* xf   = (const float*)d_in[1];
    const float* xr   = (const float*)d_in[2];
    const float* Wx   = (const float*)d_in[3];
    const float* bx   = (const float*)d_in[4];
    const float* Wx1  = (const float*)d_in[5];
    const float* bx1  = (const float*)d_in[6];
    const float* Wx2  = (const float*)d_in[7];
    const float* bx2  = (const float*)d_in[8];
    const float* Wxf  = (const float*)d_in[9];
    const float* bxf  = (const float*)d_in[10];
    const float* Wxr  = (const float*)d_in[11];
    const float* bxr  = (const float*)d_in[12];
    const float* Wm   = (const float*)d_in[13];
    const float* bm   = (const float*)d_in[14];
    const float* gam  = (const float*)d_in[15];
    const float* bet  = (const float*)d_in[16];
    const float* mean = (const float*)d_in[17];
    const float* var  = (const float*)d_in[18];
    float* out = (float*)d_out;

    const int proj_smem = PROJ_SMEM_FLOATS * 4;
    const int attn_smem = ATTN_SMEM_HALFS * 2;
    const int conv_smem = CONV_SMEM_BYTES;
    cudaFuncSetAttribute(proj_kernel, cudaFuncAttributeMaxDynamicSharedMemorySize, proj_smem);
    cudaFuncSetAttribute(attn_mma_kernel, cudaFuncAttributeMaxDynamicSharedMemorySize, attn_smem);
    cudaFuncSetAttribute(conv_mma_kernel, cudaFuncAttributeMaxDynamicSharedMemorySize, conv_smem);

    proj_kernel<<<B * H, 256, proj_smem>>>(x, xf, xr, Wx, bx, Wx1, bx1,
                                           Wx2, bx2, Wxf, bxf, Wxr, bxr);
    wprep_kernel<<<54, 192>>>(Wm);
    attn_mma_kernel<<<dim3(H, B), 256, attn_smem>>>(x);
    conv_mma_kernel<<<dim3(H, B), 256, conv_smem>>>(bm, gam, bet, mean, var, out);
}

// round 12
// speedup vs baseline: 6.2324x; 1.0671x over previous
#include <cuda_runtime.h>
#include <cuda_fp16.h>
#include <cstdint>

// Problem constants
constexpr int C   = 64;
constexpr int H   = 128;
constexpr int W   = 128;
constexpr int HW  = H * W;          // 16384
constexpr int B   = 8;
constexpr int C3  = 192;

// ---------------------------------------------------------------------------
// Scratch (device globals). Attention intermediates split fp16 (hi + lo);
// conv operands are plain fp16 (validated error model: rel_err ~3e-4).
// ---------------------------------------------------------------------------
__device__ __half g_x1h[(size_t)B * H * C * W], g_x1l[(size_t)B * H * C * W];
__device__ __half g_x2h[(size_t)B * H * C * W], g_x2l[(size_t)B * H * C * W];
__device__ __half g_xfh[(size_t)B * H * C * W], g_xfl[(size_t)B * H * C * W];
__device__ __half g_xrh[(size_t)B * H * C * W], g_xrl[(size_t)B * H * C * W];
__device__ __half g_xpth[(size_t)B * H * W * C], g_xptl[(size_t)B * H * W * C];
__device__ __half g_inh[(size_t)B * H * W * C3];
__device__ __half g_wh16[54 * 192 * 32];

// ---------------------------------------------------------------------------
// Helpers
// ---------------------------------------------------------------------------
__device__ __forceinline__ void cpa16(void* dst, const void* src) {
    uint32_t d = (uint32_t)__cvta_generic_to_shared(dst);
    asm volatile("cp.async.cg.shared.global [%0], [%1], 16;" :: "r"(d), "l"(src));
}
#define CP_COMMIT() asm volatile("cp.async.commit_group;" ::: "memory")
#define CP_WAIT1()  asm volatile("cp.async.wait_group 1;" ::: "memory")
#define CP_WAIT2()  asm volatile("cp.async.wait_group 2;" ::: "memory")

__device__ __forceinline__ void mma16816(float acc[4], uint32_t a0, uint32_t a1,
                                         uint32_t a2, uint32_t a3,
                                         uint32_t b0, uint32_t b1) {
    asm volatile(
        "mma.sync.aligned.m16n8k16.row.col.f32.f16.f16.f32 "
        "{%0,%1,%2,%3}, {%4,%5,%6,%7}, {%8,%9}, {%0,%1,%2,%3};"
        : "+f"(acc[0]), "+f"(acc[1]), "+f"(acc[2]), "+f"(acc[3])
        : "r"(a0), "r"(a1), "r"(a2), "r"(a3), "r"(b0), "r"(b1));
}

__device__ __forceinline__ void ldsm4(uint32_t& r0, uint32_t& r1, uint32_t& r2,
                                      uint32_t& r3, const __half* p) {
    uint32_t a = (uint32_t)__cvta_generic_to_shared(p);
    asm volatile("ldmatrix.sync.aligned.m8n8.x4.shared.b16 {%0,%1,%2,%3}, [%4];"
                 : "=r"(r0), "=r"(r1), "=r"(r2), "=r"(r3) : "r"(a));
}

__device__ __forceinline__ void split16(float v, __half& hi, __half& lo) {
    hi = __float2half_rn(v);
    lo = __float2half_rn(v - __half2float(hi));
}

// ---------------------------------------------------------------------------
// Kernel 1: tensor-core pointwise projections (3-term fp16 split).
// One CTA per (b,h). GEMMs: out[64 o][128 w] = W[64][64] @ in[64][128],
// chained: xp = Wx@x; x1 = Wx1@xp; x2 = Wx2@xp; xfp = Wxf@xf; xrp = Wxr@xr.
// A = W [o][c] row-major; B = in [w][c] (mma "col" layout). Stride 72 halfs.
// ---------------------------------------------------------------------------

#define PJS 72
#define PO_WH  0
#define PO_WL  4608
#define PO_INH 9216
#define PO_INL 18432
#define PO_TMP 27648            // fp32 [64][129] staging (16512 halfs)
#define PROJ_SMEM_HALFS (27648 + 16512)

__global__ __launch_bounds__(256, 2) void proj_mma_kernel(
    const float* __restrict__ x, const float* __restrict__ xf, const float* __restrict__ xr,
    const float* __restrict__ Wx,  const float* __restrict__ bx,
    const float* __restrict__ Wx1, const float* __restrict__ bx1,
    const float* __restrict__ Wx2, const float* __restrict__ bx2,
    const float* __restrict__ Wxf, const float* __restrict__ bxf,
    const float* __restrict__ Wxr, const float* __restrict__ bxr) {
    extern __shared__ __align__(16) __half smh[];
    __half* sWh  = smh + PO_WH;
    __half* sWl  = smh + PO_WL;
    __half* sInH = smh + PO_INH;
    __half* sInL = smh + PO_INL;
    float*  sTmp = (float*)(smh + PO_TMP);   // [64][129]

    const int tid = threadIdx.x;
    const int b   = blockIdx.x >> 7;
    const int h   = blockIdx.x & 127;
    const size_t bh = (size_t)b * 128 + h;
    const size_t gbase = (size_t)b * C * HW + (size_t)h * W;

    const int lane = tid & 31;
    const int wid = tid >> 5;
    const int lr = lane >> 2;
    const int lc2 = (lane & 3) * 2;
    const int grp = lane >> 3;
    const int gr  = lane & 7;
    const int aoffW = ((grp & 1) * 8 + gr) * PJS + (grp >> 1) * 8;
    const int boffI = ((grp >> 1) * 8 + gr) * PJS + (grp & 1) * 8;
    const int m0 = (wid & 1) * 32;    // 2 M-groups of 32 (o)
    const int n0 = (wid >> 1) * 32;   // 4 N-groups of 32 (w)

    auto loadW = [&](const float* Wg) {
        for (int i = tid; i < 4096; i += 256) {
            int o = i >> 6, c = i & 63;
            __half hi, lo;
            split16(Wg[i], hi, lo);
            sWh[o * PJS + c] = hi;
            sWl[o * PJS + c] = lo;
        }
    };
    auto loadTmp = [&](const float* src) {
        for (int i = tid; i < 8192; i += 256) {
            int c = i >> 7, p = i & 127;
            sTmp[c * 129 + p] = src[gbase + (size_t)c * HW + p];
        }
    };
    auto transSplit = [&]() {
        for (int i = tid; i < 8192; i += 256) {
            int c = i & 63, w = i >> 6;
            __half hi, lo;
            split16(sTmp[c * 129 + w], hi, lo);
            sInH[w * PJS + c] = hi;
            sInL[w * PJS + c] = lo;
        }
    };

    float acc[2][4][4];
    auto gemm3 = [&]() {
#pragma unroll
        for (int mt = 0; mt < 2; mt++)
#pragma unroll
            for (int nf = 0; nf < 4; nf++)
#pragma unroll
                for (int i = 0; i < 4; i++) acc[mt][nf][i] = 0.f;
#pragma unroll
        for (int ks = 0; ks < 4; ks++) {
            const int k0 = ks * 16;
            uint32_t bhf[4][2], blf[4][2];
#pragma unroll
            for (int ntp = 0; ntp < 2; ntp++) {
                const int nb = (n0 + ntp * 16) * PJS + k0 + boffI;
                ldsm4(bhf[ntp * 2][0], bhf[ntp * 2][1], bhf[ntp * 2 + 1][0],
                      bhf[ntp * 2 + 1][1], sInH + nb);
                ldsm4(blf[ntp * 2][0], blf[ntp * 2][1], blf[ntp * 2 + 1][0],
                      blf[ntp * 2 + 1][1], sInL + nb);
            }
#pragma unroll
            for (int mt = 0; mt < 2; mt++) {
                const int mb = (m0 + mt * 16) * PJS + k0 + aoffW;
                uint32_t ah0, ah1, ah2, ah3, al0, al1, al2, al3;
                ldsm4(ah0, ah1, ah2, ah3, sWh + mb);
                ldsm4(al0, al1, al2, al3, sWl + mb);
#pragma unroll
                for (int nf = 0; nf < 4; nf++)
                    mma16816(acc[mt][nf], ah0, ah1, ah2, ah3, bhf[nf][0], bhf[nf][1]);
#pragma unroll
                for (int nf = 0; nf < 4; nf++)
                    mma16816(acc[mt][nf], al0, al1, al2, al3, bhf[nf][0], bhf[nf][1]);
#pragma unroll
                for (int nf = 0; nf < 4; nf++)
                    mma16816(acc[mt][nf], ah0, ah1, ah2, ah3, blf[nf][0], blf[nf][1]);
            }
        }
    };

    // write fragments (+bias) as split fp16 [c][w] global
    auto storeCW = [&](const float* bias, __half* dh, __half* dl) {
#pragma unroll
        for (int mt = 0; mt < 2; mt++) {
            const int ob = m0 + mt * 16 + lr;
            const float b0 = __ldg(bias + ob);
            const float b1 = __ldg(bias + ob + 8);
#pragma unroll
            for (int nf = 0; nf < 4; nf++) {
                const int wcol = n0 + nf * 8 + lc2;
                __half h0, l0, h1, l1;
                split16(acc[mt][nf][0] + b0, h0, l0);
                split16(acc[mt][nf][1] + b0, h1, l1);
                size_t rb = (bh * 64 + ob) * 128 + wcol;
                *(__half2*)(dh + rb) = __halves2half2(h0, h1);
                *(__half2*)(dl + rb) = __halves2half2(l0, l1);
                split16(acc[mt][nf][2] + b1, h0, l0);
                split16(acc[mt][nf][3] + b1, h1, l1);
                rb += (size_t)8 * 128;
                *(__half2*)(dh + rb) = __halves2half2(h0, h1);
                *(__half2*)(dl + rb) = __halves2half2(l0, l1);
            }
        }
    };

    // ---- xp chain ----
    loadTmp(x);
    __syncthreads();
    transSplit();
    loadW(Wx);
    __syncthreads();
    gemm3();
    __syncthreads();
    // xp (+bias) -> sIn transposed [w][c]
    {
#pragma unroll
        for (int mt = 0; mt < 2; mt++) {
            const int ob = m0 + mt * 16 + lr;
            const float b0 = __ldg(bx + ob);
            const float b1 = __ldg(bx + ob + 8);
#pragma unroll
            for (int nf = 0; nf < 4; nf++) {
#pragma unroll
                for (int i = 0; i < 4; i++) {
                    int o = ob + ((i & 2) ? 8 : 0);
                    int w = n0 + nf * 8 + lc2 + (i & 1);
                    __half hi, lo;
                    split16(acc[mt][nf][i] + ((i & 2) ? b1 : b0), hi, lo);
                    sInH[w * PJS + o] = hi;
                    sInL[w * PJS + o] = lo;
                }
            }
        }
    }
    loadW(Wx1);
    __syncthreads();
    // dump xpt to global (coalesced) + x1 GEMM
    {
        __half* gh = g_xpth + bh * 128 * 64;
        __half* gl = g_xptl + bh * 128 * 64;
        for (int i = tid; i < 1024; i += 256) {
            int r = i >> 3, g = i & 7;
            *(uint4*)(gh + r * 64 + g * 8) = *(const uint4*)(sInH + r * PJS + g * 8);
            *(uint4*)(gl + r * 64 + g * 8) = *(const uint4*)(sInL + r * PJS + g * 8);
        }
    }
    gemm3();
    storeCW(bx1, g_x1h, g_x1l);
    __syncthreads();
    loadW(Wx2);
    loadTmp(xf);
    __syncthreads();
    gemm3();
    storeCW(bx2, g_x2h, g_x2l);
    __syncthreads();
    // ---- xfp ----
    transSplit();
    loadW(Wxf);
    __syncthreads();
    gemm3();
    storeCW(bxf, g_xfh, g_xfl);
    loadTmp(xr);
    __syncthreads();
    // ---- xrp ----
    transSplit();
    loadW(Wxr);
    __syncthreads();
    gemm3();
    storeCW(bxr, g_xrh, g_xrl);
}

// ---------------------------------------------------------------------------
// Kernel 2: tensor-core attention + conv-input packing (unchanged from R7).
// ---------------------------------------------------------------------------

#define AS1 136
#define ASP 72
#define ASS 72
#define ASF 129
#define O_X1H 0
#define O_X1L 8704
#define O_XFH 17408
#define O_XFL 26112
#define O_PH  34816
#define O_PL  44032
#define ATTN_SMEM_HALFS 53248   // 106496 bytes

__global__ __launch_bounds__(256, 2) void attn_mma_kernel(const float* __restrict__ x) {
    extern __shared__ __align__(16) __half smh[];
    __half* sX1h = smh + O_X1H;
    __half* sX1l = smh + O_X1L;
    __half* sXfh = smh + O_XFH;
    __half* sXfl = smh + O_XFL;
    __half* sPh  = smh + O_PH;
    __half* sPl  = smh + O_PL;
    __half* sSh  = smh + O_XFH;            // alias over sXf after GEMM1
    __half* sSl  = smh + O_XFH + 4608;
    float*  sF   = (float*)smh;            // alias over sX1 (8256 floats)

    const int tid = threadIdx.x;
    const int h = blockIdx.x, b = blockIdx.y;
    const size_t bh = (size_t)b * 128 + h;

    const int lane = tid & 31;
    const int wid = tid >> 5;
    const int lr = lane >> 2;
    const int lc2 = (lane & 3) * 2;
    const int grp = lane >> 3;
    const int gr  = lane & 7;

    uint32_t* outh = (uint32_t*)g_inh;
    const size_t wbase = bh * 128 * 96;

    // ---- load xpt ----
    {
        const __half* srcH = g_xpth + bh * 128 * 64;
        const __half* srcL = g_xptl + bh * 128 * 64;
        for (int idx = tid; idx < 1024; idx += 256) {
            int r = idx >> 3, g = idx & 7;
            *(uint4*)(sPh + r * ASP + g * 8) = *(const uint4*)(srcH + r * 64 + g * 8);
            *(uint4*)(sPl + r * ASP + g * 8) = *(const uint4*)(srcL + r * 64 + g * 8);
        }
    }
    // ---- pack x (channels 128..191) ----
    {
        const size_t xbase = (size_t)b * C * HW + (size_t)h * W;
        for (int idx = tid; idx < 8192; idx += 256) {
            int c = idx >> 7, w = idx & 127;
            sF[c * ASF + w] = x[xbase + (size_t)c * HW + w];
        }
        __syncthreads();
        for (int idx = tid; idx < 4096; idx += 256) {
            int q = idx & 31, w = idx >> 5;
            int c = q * 2;
            __half2 ph = __halves2half2(__float2half_rn(sF[c * ASF + w]),
                                        __float2half_rn(sF[(c + 1) * ASF + w]));
            outh[wbase + (size_t)w * 96 + 64 + q] = *(uint32_t*)&ph;
        }
    }

    const int aoff1 = ((grp & 1) * 8 + gr) * AS1 + (grp >> 1) * 8;
    const int boff1 = ((grp >> 1) * 8 + gr) * AS1 + (grp & 1) * 8;
    const int aoffS = ((grp & 1) * 8 + gr) * ASS + (grp >> 1) * 8;
    const int boffP = ((grp >> 1) * 8 + gr) * ASP + (grp & 1) * 8;

    for (int pass = 0; pass < 2; pass++) {
        const __half* gAh = pass ? g_x2h : g_x1h;
        const __half* gAl = pass ? g_x2l : g_x1l;
        const __half* gBh = pass ? g_xrh : g_xfh;
        const __half* gBl = pass ? g_xrl : g_xfl;

        __syncthreads();
        {
            const size_t sb = bh * 64 * 128;
            for (int idx = tid; idx < 1024; idx += 256) {
                int r = idx >> 4, g = idx & 15;
                *(uint4*)(sX1h + r * AS1 + g * 8) = *(const uint4*)(gAh + sb + r * 128 + g * 8);
                *(uint4*)(sX1l + r * AS1 + g * 8) = *(const uint4*)(gAl + sb + r * 128 + g * 8);
                *(uint4*)(sXfh + r * AS1 + g * 8) = *(const uint4*)(gBh + sb + r * 128 + g * 8);
                *(uint4*)(sXfl + r * AS1 + g * 8) = *(const uint4*)(gBl + sb + r * 128 + g * 8);
            }
        }
        __syncthreads();

        // ---- GEMM1: score = x1 @ xfp^T ----
        float sacc[4][4];
#pragma unroll
        for (int nf = 0; nf < 4; nf++)
#pragma unroll
            for (int i = 0; i < 4; i++) sacc[nf][i] = 0.f;
        {
            const int m0 = (wid & 3) * 16, n0 = (wid >> 2) * 32;
#pragma unroll
            for (int ks = 0; ks < 8; ks++) {
                const int k0 = ks * 16;
                uint32_t bhf[4][2], blf[4][2];
#pragma unroll
                for (int ntp = 0; ntp < 2; ntp++) {
                    const int nb = (n0 + ntp * 16) * AS1 + k0 + boff1;
                    ldsm4(bhf[ntp * 2][0], bhf[ntp * 2][1], bhf[ntp * 2 + 1][0],
                          bhf[ntp * 2 + 1][1], sXfh + nb);
                    ldsm4(blf[ntp * 2][0], blf[ntp * 2][1], blf[ntp * 2 + 1][0],
                          blf[ntp * 2 + 1][1], sXfl + nb);
                }
                const int mb = m0 * AS1 + k0 + aoff1;
                uint32_t ah0, ah1, ah2, ah3, al0, al1, al2, al3;
                ldsm4(ah0, ah1, ah2, ah3, sX1h + mb);
                ldsm4(al0, al1, al2, al3, sX1l + mb);
#pragma unroll
                for (int nf = 0; nf < 4; nf++)
                    mma16816(sacc[nf], ah0, ah1, ah2, ah3, bhf[nf][0], bhf[nf][1]);
#pragma unroll
                for (int nf = 0; nf < 4; nf++)
                    mma16816(sacc[nf], al0, al1, al2, al3, bhf[nf][0], bhf[nf][1]);
#pragma unroll
                for (int nf = 0; nf < 4; nf++)
                    mma16816(sacc[nf], ah0, ah1, ah2, ah3, blf[nf][0], blf[nf][1]);
            }
        }
        __syncthreads();

        // ---- score -> smem split fp16 ----
        {
            const int m0 = (wid & 3) * 16, n0 = (wid >> 2) * 32;
#pragma unroll
            for (int nf = 0; nf < 4; nf++)
#pragma unroll
                for (int i = 0; i < 4; i++) {
                    int row = m0 + lr + (i >= 2 ? 8 : 0);
                    int col = n0 + nf * 8 + lc2 + (i & 1);
                    __half hi, lo;
                    split16(sacc[nf][i], hi, lo);
                    sSh[row * ASS + col] = hi;
                    sSl[row * ASS + col] = lo;
                }
        }
        __syncthreads();

        // ---- GEMM2: feat = score @ xp ----
        float facc[2][4][4];
#pragma unroll
        for (int mt = 0; mt < 2; mt++)
#pragma unroll
            for (int nf = 0; nf < 4; nf++)
#pragma unroll
                for (int i = 0; i < 4; i++) facc[mt][nf][i] = 0.f;
        {
            const int m0 = (wid & 1) * 32, n0 = (wid >> 1) * 32;
#pragma unroll
            for (int ks = 0; ks < 4; ks++) {
                const int k0 = ks * 16;
                uint32_t bhf[4][2], blf[4][2];
#pragma unroll
                for (int ntp = 0; ntp < 2; ntp++) {
                    const int nb = (n0 + ntp * 16) * ASP + k0 + boffP;
                    ldsm4(bhf[ntp * 2][0], bhf[ntp * 2][1], bhf[ntp * 2 + 1][0],
                          bhf[ntp * 2 + 1][1], sPh + nb);
                    ldsm4(blf[ntp * 2][0], blf[ntp * 2][1], blf[ntp * 2 + 1][0],
                          blf[ntp * 2 + 1][1], sPl + nb);
                }
#pragma unroll
                for (int mt = 0; mt < 2; mt++) {
                    const int mb = (m0 + mt * 16) * ASS + k0 + aoffS;
                    uint32_t ah0, ah1, ah2, ah3, al0, al1, al2, al3;
                    ldsm4(ah0, ah1, ah2, ah3, sSh + mb);
                    ldsm4(al0, al1, al2, al3, sSl + mb);
#pragma unroll
                    for (int nf = 0; nf < 4; nf++)
                        mma16816(facc[mt][nf], ah0, ah1, ah2, ah3, bhf[nf][0], bhf[nf][1]);
#pragma unroll
                    for (int nf = 0; nf < 4; nf++)
                        mma16816(facc[mt][nf], al0, al1, al2, al3, bhf[nf][0], bhf[nf][1]);
#pragma unroll
                    for (int nf = 0; nf < 4; nf++)
                        mma16816(facc[mt][nf], ah0, ah1, ah2, ah3, blf[nf][0], blf[nf][1]);
                }
            }
        }
        {
            const int m0 = (wid & 1) * 32, n0 = (wid >> 1) * 32;
#pragma unroll
            for (int mt = 0; mt < 2; mt++)
#pragma unroll
                for (int nf = 0; nf < 4; nf++)
#pragma unroll
                    for (int i = 0; i < 4; i++) {
                        int row = m0 + mt * 16 + lr + (i >= 2 ? 8 : 0);
                        int col = n0 + nf * 8 + lc2 + (i & 1);
                        sF[row * ASF + col] = facc[mt][nf][i];
                    }
        }
        __syncthreads();

        // ---- pack feat (channels pass*64 ..) ----
        for (int idx = tid; idx < 4096; idx += 256) {
            int q = idx & 31, w = idx >> 5;
            int c = q * 2;
            __half2 ph = __halves2half2(__float2half_rn(sF[c * ASF + w]),
                                        __float2half_rn(sF[(c + 1) * ASF + w]));
            outh[wbase + (size_t)w * 96 + pass * 32 + q] = *(uint32_t*)&ph;
        }
    }
}

// ---------------------------------------------------------------------------
// Kernel 3a: weight prep (fp16).
// ---------------------------------------------------------------------------
__global__ void wprep_kernel(const float* __restrict__ Wm) {
    const int kc = blockIdx.x;       // 0..53
    const int o  = threadIdx.x;      // 0..191
    const int tap = kc / 6;
    const int ch0 = (kc - tap * 6) * 32;
#pragma unroll
    for (int j = 0; j < 32; j++) {
        float v  = Wm[((size_t)o * 192 + ch0 + j) * 9 + tap];
        g_wh16[((size_t)kc * 192 + o) * 32 + j] = __float2half_rn(v);
    }
}

// ---------------------------------------------------------------------------
// Kernel 3b: pure fp16 mma.sync implicit-GEMM conv + BN + ReLU.
// 4-stage cp.async pipeline, ONE sync per K-chunk.
// ---------------------------------------------------------------------------

#define AST 40
#define A_TILE (192 * AST)
#define B_TILE (128 * AST)
#define CONV_SMEM_BYTES ((4 * A_TILE + 4 * B_TILE) * 2 + 384 * 4)

__global__ __launch_bounds__(256, 2) void conv_mma_kernel(
    const float* __restrict__ bm, const float* __restrict__ gamma,
    const float* __restrict__ beta, const float* __restrict__ mean,
    const float* __restrict__ var, float* __restrict__ out) {
    extern __shared__ __align__(16) __half smh[];
    __half* sAh = smh;                        // [4][A_TILE]
    __half* sBh = sAh + 4 * A_TILE;           // [4][B_TILE]
    float* ssc = (float*)(sBh + 4 * B_TILE);
    float* sbi = ssc + 192;

    const int tid = threadIdx.x;
    const int h = blockIdx.x, b = blockIdx.y;

    if (tid < 192) {
        float scv = gamma[tid] * rsqrtf(var[tid] + 1e-4f);
        ssc[tid] = scv;
        sbi[tid] = (bm[tid] - mean[tid]) * scv + beta[tid];
    }

    const int lane = tid & 31;
    const int wid = tid >> 5;
    const int wm = wid & 1;
    const int wn = wid >> 1;
    const int lr = lane >> 2;
    const int lc2 = (lane & 3) * 2;
    const int grp = lane >> 3;
    const int gr  = lane & 7;
    const int aoff = ((grp & 1) * 8 + gr) * AST + (grp >> 1) * 8;
    const int boff = ((grp >> 1) * 8 + gr) * AST + (grp & 1) * 8;

    float acc[6][4][4];
#pragma unroll
    for (int mt = 0; mt < 6; mt++)
#pragma unroll
        for (int nt = 0; nt < 4; nt++)
#pragma unroll
            for (int i = 0; i < 4; i++) acc[mt][nt][i] = 0.f;

    auto stage = [&](int kc, int buf) {
        const int tap = kc / 6;
        const int ch0 = (kc - tap * 6) * 32;
        const int dh = tap / 3 - 1;
        const int dw = tap - (tap / 3) * 3 - 1;
        const int row = h + dh;
        const bool rok = ((unsigned)row < 128u);
        const __half* wh = g_wh16 + (size_t)kc * 6144;
#pragma unroll
        for (int i = 0; i < 3; i++) {
            int idx = tid + i * 256;
            int r = idx >> 2, g = idx & 3;
            cpa16(sAh + buf * A_TILE + r * AST + g * 8, wh + r * 32 + g * 8);
        }
        const size_t rowbase = ((size_t)(b * 128 + row) * 128) * 192;
#pragma unroll
        for (int i = 0; i < 2; i++) {
            int idx = tid + i * 256;
            int r = idx >> 2, g = idx & 3;
            int wsrc = r + dw;
            bool ok = rok && ((unsigned)wsrc < 128u);
            __half* dh_ = sBh + buf * B_TILE + r * AST + g * 8;
            if (ok) {
                cpa16(dh_, g_inh + rowbase + (size_t)wsrc * 192 + ch0 + g * 8);
            } else {
                *(uint4*)dh_ = make_uint4(0, 0, 0, 0);
            }
        }
    };

    stage(0, 0); CP_COMMIT();
    stage(1, 1); CP_COMMIT();
    stage(2, 2); CP_COMMIT();

    for (int kc = 0; kc < 54; kc++) {
        const int buf = kc & 3;
        CP_WAIT2();
        __syncthreads();
        if (kc + 3 < 54) stage(kc + 3, (kc + 3) & 3);
        CP_COMMIT();

        const __half* bAh = sAh + buf * A_TILE;
        const __half* bBh = sBh + buf * B_TILE;

#pragma unroll
        for (int ks = 0; ks < 2; ks++) {
            const int kk = ks * 16;
            uint32_t bh[4][2];
#pragma unroll
            for (int ntp = 0; ntp < 2; ntp++) {
                const int nb = (wn * 32 + ntp * 16) * AST + kk + boff;
                ldsm4(bh[ntp * 2][0], bh[ntp * 2][1], bh[ntp * 2 + 1][0],
                      bh[ntp * 2 + 1][1], bBh + nb);
            }
#pragma unroll
            for (int mt = 0; mt < 6; mt++) {
                const int mb = (wm * 96 + mt * 16) * AST + kk + aoff;
                uint32_t ah0, ah1, ah2, ah3;
                ldsm4(ah0, ah1, ah2, ah3, bAh + mb);
#pragma unroll
                for (int nt = 0; nt < 4; nt++)
                    mma16816(acc[mt][nt], ah0, ah1, ah2, ah3, bh[nt][0], bh[nt][1]);
            }
        }
    }

#pragma unroll
    for (int mt = 0; mt < 6; mt++) {
        int o0 = wm * 96 + mt * 16 + lr;
        float s0 = ssc[o0],     bi0 = sbi[o0];
        float s1 = ssc[o0 + 8], bi1 = sbi[o0 + 8];
#pragma unroll
        for (int nt = 0; nt < 4; nt++) {
            int wcol = wn * 32 + nt * 8 + lc2;
            float2 v0, v1;
            v0.x = fmaxf(acc[mt][nt][0] * s0 + bi0, 0.f);
            v0.y = fmaxf(acc[mt][nt][1] * s0 + bi0, 0.f);
            v1.x = fmaxf(acc[mt][nt][2] * s1 + bi1, 0.f);
            v1.y = fmaxf(acc[mt][nt][3] * s1 + bi1, 0.f);
            size_t p0 = (((size_t)b * C3 + o0)     * H + h) * W + wcol;
            size_t p1 = (((size_t)b * C3 + o0 + 8) * H + h) * W + wcol;
            *(float2*)(out + p0) = v0;
            *(float2*)(out + p1) = v1;
        }
    }
}

// ---------------------------------------------------------------------------

extern "C" void kernel_launch(void* const* d_in, const int* in_sizes, int n_in,
                              void* d_out, int out_size) {
    const float* x    = (const float*)d_in[0];
    const float* xf   = (const float*)d_in[1];
    const float* xr   = (const float*)d_in[2];
    const float* Wx   = (const float*)d_in[3];
    const float* bx   = (const float*)d_in[4];
    const float* Wx1  = (const float*)d_in[5];
    const float* bx1  = (const float*)d_in[6];
    const float* Wx2  = (const float*)d_in[7];
    const float* bx2  = (const float*)d_in[8];
    const float* Wxf  = (const float*)d_in[9];
    const float* bxf  = (const float*)d_in[10];
    const float* Wxr  = (const float*)d_in[11];
    const float* bxr  = (const float*)d_in[12];
    const float* Wm   = (const float*)d_in[13];
    const float* bm   = (const float*)d_in[14];
    const float* gam  = (const float*)d_in[15];
    const float* bet  = (const float*)d_in[16];
    const float* mean = (const float*)d_in[17];
    const float* var  = (const float*)d_in[18];
    float* out = (float*)d_out;

    const int proj_smem = PROJ_SMEM_HALFS * 2;
    const int attn_smem = ATTN_SMEM_HALFS * 2;
    const int conv_smem = CONV_SMEM_BYTES;
    cudaFuncSetAttribute(proj_mma_kernel, cudaFuncAttributeMaxDynamicSharedMemorySize, proj_smem);
    cudaFuncSetAttribute(attn_mma_kernel, cudaFuncAttributeMaxDynamicSharedMemorySize, attn_smem);
    cudaFuncSetAttribute(conv_mma_kernel, cudaFuncAttributeMaxDynamicSharedMemorySize, conv_smem);

    proj_mma_kernel<<<B * H, 256, proj_smem>>>(x, xf, xr, Wx, bx, Wx1, bx1,
                                               Wx2, bx2, Wxf, bxf, Wxr, bxr);
    wprep_kernel<<<54, 192>>>(Wm);
    attn_mma_kernel<<<dim3(H, B), 256, attn_smem>>>(x);
    conv_mma_kernel<<<dim3(H, B), 256, conv_smem>>>(bm, gam, bet, mean, var, out);
}